// round 5
// baseline (speedup 1.0000x reference)
#include <cuda_runtime.h>
#include <math.h>
#include <stdint.h>

// Problem dims
constexpr int CB  = 4;
constexpr int CS  = 1024;
constexpr int CD  = 1024;
constexpr int CH  = 16;
constexpr int CDK = 64;
constexpr int BH   = CB * CH;   // 64
constexpr int ROWS = CB * CS;   // 4096
constexpr float LN_EPS = 1e-5f;

// Scratch (device globals: no cudaMalloc allowed)
__device__ float g_valid[ROWS];
__device__ float g_Q[(size_t)BH * CS * CDK];
__device__ float g_K[(size_t)BH * CS * CDK];
__device__ float g_V[(size_t)BH * CS * CDK];
__device__ float g_Z[(size_t)ROWS * CD];
__device__ float g_Hb[(size_t)ROWS * CD];
__device__ float g_F[(size_t)ROWS * CD];
__device__ float g_G[(size_t)ROWS * CD];

// ---------------- helpers ----------------
__device__ __forceinline__ float warpSum(float v) {
    #pragma unroll
    for (int o = 16; o; o >>= 1) v += __shfl_xor_sync(0xffffffffu, v, o);
    return v;
}
__device__ __forceinline__ uint32_t f2tf(float f) {
    uint32_t u;
    asm("cvt.rna.tf32.f32 %0, %1;" : "=r"(u) : "f"(f));
    return u;
}
__device__ __forceinline__ void mma8(float c[4], const uint32_t a[4], const uint32_t b[2]) {
    asm volatile(
        "mma.sync.aligned.m16n8k8.row.col.f32.tf32.tf32.f32 "
        "{%0,%1,%2,%3},{%4,%5,%6,%7},{%8,%9},{%0,%1,%2,%3};"
        : "+f"(c[0]), "+f"(c[1]), "+f"(c[2]), "+f"(c[3])
        : "r"(a[0]), "r"(a[1]), "r"(a[2]), "r"(a[3]), "r"(b[0]), "r"(b[1]));
}
__device__ __forceinline__ void cp16(void* dst, const void* src) {
    uint32_t d = (uint32_t)__cvta_generic_to_shared(dst);
    asm volatile("cp.async.cg.shared.global [%0], [%1], 16;" :: "r"(d), "l"(src));
}
__device__ __forceinline__ void cp_commit() { asm volatile("cp.async.commit_group;"); }
__device__ __forceinline__ void cp_wait0()  { asm volatile("cp.async.wait_group 0;"); }

// ---------------- pipelined tf32 MMA GEMM core ----------------
// Block tile 128(M) x NT(N), BK=16, 2-stage cp.async double buffer.
// 256 threads = 8 warps (4 row x 2 col); each warp 32(M) x NT/2(N).
// NN: B stored [K,N] row-major (ldb), NT must be 64. NT(!NN): B stored [N,K] row-major.
template<bool NN, int NT>
__device__ __forceinline__ void gemm_pipe(const float* __restrict__ A, size_t lda,
                                          const float* __restrict__ B, size_t ldb,
                                          int K, float acc[2][NT/16][4]) {
    constexpr int NS = NT / 16;                 // n-frags per warp
    __shared__ float sA[2][128][20];            // [buf][row][k], stride 20 conflict-free
    constexpr int BFLOATS = NN ? (16 * 72) : (NT * 20);
    __shared__ float sB[2 * BFLOATS];
    const int t = threadIdx.x, lane = t & 31, w = t >> 5;
    const int wr = w >> 1, wc = w & 1;
    const int rA = lane >> 2, qq = lane & 3;

    auto loadTiles = [&](int k0, int buf) {
        #pragma unroll
        for (int i = 0; i < 2; i++) {           // A: 128x16 = 512 chunks
            int id = t + i * 256;
            int row = id >> 2, c4 = (id & 3) << 2;
            cp16(&sA[buf][row][c4], A + (size_t)row * lda + k0 + c4);
        }
        if (NN) {                               // B: 16x64 = 256 chunks
            int k = t >> 4, n4 = (t & 15) << 2;
            cp16(&sB[buf * BFLOATS + k * 72 + n4], B + (size_t)(k0 + k) * ldb + n4);
        } else {                                // B: NTx16 chunks
            #pragma unroll
            for (int i = 0; i < NT / 64; i++) {
                int id = t + i * 256;
                int n = id >> 2, c4 = (id & 3) << 2;
                cp16(&sB[buf * BFLOATS + n * 20 + c4], B + (size_t)n * ldb + k0 + c4);
            }
        }
        cp_commit();
    };

    const int nit = K >> 4;
    loadTiles(0, 0);
    for (int i = 0; i < nit; i++) {
        cp_wait0();
        __syncthreads();
        const int buf = i & 1;
        if (i + 1 < nit) loadTiles((i + 1) << 4, buf ^ 1);

        #pragma unroll
        for (int ks = 0; ks < 16; ks += 8) {
            const int kc = ks + qq;
            uint32_t af[2][4];
            #pragma unroll
            for (int ms = 0; ms < 2; ms++) {
                int r0 = wr * 32 + ms * 16 + rA;
                af[ms][0] = f2tf(sA[buf][r0][kc]);
                af[ms][1] = f2tf(sA[buf][r0 + 8][kc]);
                af[ms][2] = f2tf(sA[buf][r0][kc + 4]);
                af[ms][3] = f2tf(sA[buf][r0 + 8][kc + 4]);
            }
            uint32_t bf[NS][2];
            #pragma unroll
            for (int ns = 0; ns < NS; ns++) {
                int n0 = wc * (NT / 2) + ns * 8 + rA;
                if (NN) {
                    bf[ns][0] = f2tf(sB[buf * BFLOATS + kc * 72 + n0]);
                    bf[ns][1] = f2tf(sB[buf * BFLOATS + (kc + 4) * 72 + n0]);
                } else {
                    bf[ns][0] = f2tf(sB[buf * BFLOATS + n0 * 20 + kc]);
                    bf[ns][1] = f2tf(sB[buf * BFLOATS + n0 * 20 + kc + 4]);
                }
            }
            #pragma unroll
            for (int ms = 0; ms < 2; ms++)
                #pragma unroll
                for (int ns = 0; ns < NS; ns++)
                    mma8(acc[ms][ns], af[ms], bf[ns]);
        }
        __syncthreads();
    }
}

// ---------------- valid-row flags ----------------
__global__ void k_valid(const float* __restrict__ x, float* __restrict__ valid) {
    int row = blockIdx.x;
    const float* xr = x + (size_t)row * CD;
    int any = 0;
    for (int i = threadIdx.x; i < CD; i += blockDim.x) any |= (xr[i] != 0.0f);
    any = __syncthreads_or(any);
    if (threadIdx.x == 0) valid[row] = any ? 1.0f : 0.0f;
}

// ---------------- QKV projection (tf32 MMA, pipelined) ----------------
// grid: (48 = 3*16, 32). out[b,h,s,e]
__global__ void __launch_bounds__(256)
k_qkv_mma(const float* __restrict__ x,
          const float* __restrict__ Wq, const float* __restrict__ Wk,
          const float* __restrict__ Wv,
          float* __restrict__ pQ, float* __restrict__ pK, float* __restrict__ pV) {
    int nt = blockIdx.x;
    int which = nt >> 4, h = nt & 15;
    int b = blockIdx.y >> 3, s0 = (blockIdx.y & 7) << 7;
    const float* W = (which == 0 ? Wq : which == 1 ? Wk : Wv) + (size_t)h * CD * CDK;
    const float* A = x + ((size_t)b * CS + s0) * CD;
    float* out = (which == 0 ? pQ : which == 1 ? pK : pV)
                 + ((size_t)(b * 16 + h) * CS + s0) * CDK;

    float acc[2][4][4] = {};
    gemm_pipe<true, 64>(A, CD, W, CDK, CD, acc);

    int lane = threadIdx.x & 31, w = threadIdx.x >> 5, wr = w >> 1, wc = w & 1;
    #pragma unroll
    for (int ms = 0; ms < 2; ms++)
        #pragma unroll
        for (int ns = 0; ns < 4; ns++) {
            int r = wr * 32 + ms * 16 + (lane >> 2);
            int c = wc * 32 + ns * 8 + ((lane & 3) << 1);
            float2 v01 = { acc[ms][ns][0], acc[ms][ns][1] };
            float2 v23 = { acc[ms][ns][2], acc[ms][ns][3] };
            *(float2*)&out[(size_t)r * CDK + c] = v01;
            *(float2*)&out[(size_t)(r + 8) * CDK + c] = v23;
        }
}

// ---------------- fused flash attention ----------------
// grid: (8 q-tiles, 64 bh), 256 threads = 8 warps; warp w owns q-rows 16w..16w+15.
__global__ void __launch_bounds__(256)
k_flash(const float* __restrict__ pQ, const float* __restrict__ pK,
        const float* __restrict__ pV, const float* __restrict__ valid,
        float* __restrict__ pZ) {
    __shared__ uint32_t sK[64][68];
    __shared__ uint32_t sV[64][72];
    const int bh = blockIdx.y, b = bh >> 4, h = bh & 15;
    const int q0 = blockIdx.x * 128;
    const int t = threadIdx.x, lane = t & 31, w = t >> 5;
    const int rA = lane >> 2;      // 0..7
    const int qq = lane & 3;       // 0..3
    const float* vbase = valid + b * CS;

    const float* Qb = pQ + ((size_t)bh * CS + q0 + w * 16) * CDK;
    uint32_t qf[8][4];
    #pragma unroll
    for (int s = 0; s < 8; s++) {
        int k = s * 8 + qq;
        qf[s][0] = f2tf(Qb[(size_t)rA * CDK + k]);
        qf[s][1] = f2tf(Qb[(size_t)(rA + 8) * CDK + k]);
        qf[s][2] = f2tf(Qb[(size_t)rA * CDK + k + 4]);
        qf[s][3] = f2tf(Qb[(size_t)(rA + 8) * CDK + k + 4]);
    }

    float acc_o[8][4] = {};
    float mA = -INFINITY, mB = -INFINITY, lA = 0.f, lB = 0.f;

    for (int kt = 0; kt < 16; kt++) {
        __syncthreads();
        const float* Kg = pK + ((size_t)bh * CS + kt * 64) * CDK;
        const float* Vg = pV + ((size_t)bh * CS + kt * 64) * CDK;
        #pragma unroll
        for (int i = 0; i < 4; i++) {
            int row = (t >> 4) + i * 16;
            int c4  = (t & 15) << 2;
            float4 kv = *(const float4*)(Kg + (size_t)row * CDK + c4);
            float4 vv = *(const float4*)(Vg + (size_t)row * CDK + c4);
            uint4 ku = { f2tf(kv.x), f2tf(kv.y), f2tf(kv.z), f2tf(kv.w) };
            uint4 vu = { f2tf(vv.x), f2tf(vv.y), f2tf(vv.z), f2tf(vv.w) };
            *(uint4*)&sK[row][c4] = ku;
            *(uint4*)&sV[row][c4] = vu;
        }
        __syncthreads();

        float accs[8][4] = {};
        #pragma unroll
        for (int s = 0; s < 8; s++) {
            int kc = s * 8 + qq;
            #pragma unroll
            for (int j = 0; j < 8; j++) {
                int n0 = j * 8 + rA;
                uint32_t bf[2] = { sK[n0][kc], sK[n0][kc + 4] };
                mma8(accs[j], qf[s], bf);
            }
        }

        float rmaxA = -INFINITY, rmaxB = -INFINITY;
        #pragma unroll
        for (int j = 0; j < 8; j++) {
            int cg = kt * 64 + j * 8 + (qq << 1);
            float cm0 = vbase[cg], cm1 = vbase[cg + 1];
            accs[j][0] = (cm0 != 0.f) ? accs[j][0] * 0.125f : -1e30f;
            accs[j][1] = (cm1 != 0.f) ? accs[j][1] * 0.125f : -1e30f;
            accs[j][2] = (cm0 != 0.f) ? accs[j][2] * 0.125f : -1e30f;
            accs[j][3] = (cm1 != 0.f) ? accs[j][3] * 0.125f : -1e30f;
            rmaxA = fmaxf(rmaxA, fmaxf(accs[j][0], accs[j][1]));
            rmaxB = fmaxf(rmaxB, fmaxf(accs[j][2], accs[j][3]));
        }
        rmaxA = fmaxf(rmaxA, __shfl_xor_sync(~0u, rmaxA, 1));
        rmaxA = fmaxf(rmaxA, __shfl_xor_sync(~0u, rmaxA, 2));
        rmaxB = fmaxf(rmaxB, __shfl_xor_sync(~0u, rmaxB, 1));
        rmaxB = fmaxf(rmaxB, __shfl_xor_sync(~0u, rmaxB, 2));

        float mnA = fmaxf(mA, rmaxA), mnB = fmaxf(mB, rmaxB);
        float aAf = __expf(mA - mnA), aBf = __expf(mB - mnB);
        mA = mnA; mB = mnB;

        float sumA = 0.f, sumB = 0.f;
        uint32_t pt[8][4];
        #pragma unroll
        for (int j = 0; j < 8; j++) {
            float p0 = __expf(accs[j][0] - mA), p1 = __expf(accs[j][1] - mA);
            float p2 = __expf(accs[j][2] - mB), p3 = __expf(accs[j][3] - mB);
            sumA += p0 + p1; sumB += p2 + p3;
            pt[j][0] = f2tf(p0); pt[j][1] = f2tf(p1);
            pt[j][2] = f2tf(p2); pt[j][3] = f2tf(p3);
            acc_o[j][0] *= aAf; acc_o[j][1] *= aAf;
            acc_o[j][2] *= aBf; acc_o[j][3] *= aBf;
        }
        sumA += __shfl_xor_sync(~0u, sumA, 1); sumA += __shfl_xor_sync(~0u, sumA, 2);
        sumB += __shfl_xor_sync(~0u, sumB, 1); sumB += __shfl_xor_sync(~0u, sumB, 2);
        lA = lA * aAf + sumA; lB = lB * aBf + sumB;

        #pragma unroll
        for (int s = 0; s < 8; s++) {
            int src0 = (lane & ~3) | (qq >> 1);
            int src1 = src0 + 2;
            uint32_t v00 = __shfl_sync(~0u, pt[s][0], src0);
            uint32_t v01 = __shfl_sync(~0u, pt[s][1], src0);
            uint32_t v10 = __shfl_sync(~0u, pt[s][2], src0);
            uint32_t v11 = __shfl_sync(~0u, pt[s][3], src0);
            uint32_t w00 = __shfl_sync(~0u, pt[s][0], src1);
            uint32_t w01 = __shfl_sync(~0u, pt[s][1], src1);
            uint32_t w10 = __shfl_sync(~0u, pt[s][2], src1);
            uint32_t w11 = __shfl_sync(~0u, pt[s][3], src1);
            uint32_t af[4];
            af[0] = (qq & 1) ? v01 : v00;
            af[1] = (qq & 1) ? v11 : v10;
            af[2] = (qq & 1) ? w01 : w00;
            af[3] = (qq & 1) ? w11 : w10;
            int kc = s * 8 + qq;
            #pragma unroll
            for (int j = 0; j < 8; j++) {
                int n0 = j * 8 + rA;
                uint32_t bf[2] = { sV[kc][n0], sV[kc + 4][n0] };
                mma8(acc_o[j], af, bf);
            }
        }
    }

    float invA = 1.f / lA, invB = 1.f / lB;
    int qrA = q0 + w * 16 + rA, qrB = qrA + 8;
    float vfA = vbase[qrA] * invA, vfB = vbase[qrB] * invB;
    #pragma unroll
    for (int j = 0; j < 8; j++) {
        int c = j * 8 + (qq << 1);
        float2 v01 = { acc_o[j][0] * vfA, acc_o[j][1] * vfA };
        float2 v23 = { acc_o[j][2] * vfB, acc_o[j][3] * vfB };
        *(float2*)&pZ[(size_t)(b * CS + qrA) * CD + h * 64 + c] = v01;
        *(float2*)&pZ[(size_t)(b * CS + qrB) * CD + h * 64 + c] = v23;
    }
}

// ---------------- residual add + LayerNorm ----------------
__global__ void k_addln(const float* __restrict__ A, const float* __restrict__ Bv,
                        const float* __restrict__ g, const float* __restrict__ bb,
                        float* __restrict__ out) {
    int row = blockIdx.x, t = threadIdx.x;
    float4 a = ((const float4*)(A  + (size_t)row * CD))[t];
    float4 b = ((const float4*)(Bv + (size_t)row * CD))[t];
    float4 v = {a.x + b.x, a.y + b.y, a.z + b.z, a.w + b.w};
    float s = v.x + v.y + v.z + v.w;
    float q = v.x * v.x + v.y * v.y + v.z * v.z + v.w * v.w;
    __shared__ float sr1[8];
    __shared__ float sr2[8];
    s = warpSum(s); q = warpSum(q);
    if ((t & 31) == 0) { sr1[t >> 5] = s; sr2[t >> 5] = q; }
    __syncthreads();
    float S = 0.f, Q = 0.f;
    #pragma unroll
    for (int i = 0; i < 8; i++) { S += sr1[i]; Q += sr2[i]; }
    float mu = S * (1.0f / CD);
    float var = Q * (1.0f / CD) - mu * mu;
    float rs = rsqrtf(var + LN_EPS);
    float4 gg = ((const float4*)g)[t];
    float4 bv2 = ((const float4*)bb)[t];
    float4 o;
    o.x = (v.x - mu) * rs * gg.x + bv2.x;
    o.y = (v.y - mu) * rs * gg.y + bv2.y;
    o.z = (v.z - mu) * rs * gg.z + bv2.z;
    o.w = (v.w - mu) * rs * gg.w + bv2.w;
    ((float4*)(out + (size_t)row * CD))[t] = o;
}

// ---------------- FC (NT GEMM, tf32 MMA, pipelined, 128x128 tile) ----------------
// grid: (8 col-tiles, 32 row-tiles)
template <bool RELU>
__global__ void __launch_bounds__(256)
k_fc_mma(const float* __restrict__ A, const float* __restrict__ W,
         const float* __restrict__ bias, const float* __restrict__ valid,
         float* __restrict__ out) {
    int j0 = blockIdx.x * 128, r0 = blockIdx.y * 128;
    float acc[2][8][4] = {};
    gemm_pipe<false, 128>(A + (size_t)r0 * CD, CD, W + (size_t)j0 * CD, CD, CD, acc);

    int lane = threadIdx.x & 31, w = threadIdx.x >> 5, wr = w >> 1, wc = w & 1;
    #pragma unroll
    for (int ms = 0; ms < 2; ms++)
        #pragma unroll
        for (int ns = 0; ns < 8; ns++) {
            int r = wr * 32 + ms * 16 + (lane >> 2);
            int c = wc * 64 + ns * 8 + ((lane & 3) << 1);
            float b0 = bias[j0 + c], b1 = bias[j0 + c + 1];
            float vf0 = valid[r0 + r], vf1 = valid[r0 + r + 8];
            float t0 = acc[ms][ns][0] + b0, t1 = acc[ms][ns][1] + b1;
            float t2 = acc[ms][ns][2] + b0, t3 = acc[ms][ns][3] + b1;
            if (RELU) {
                t0 = fmaxf(t0, 0.f); t1 = fmaxf(t1, 0.f);
                t2 = fmaxf(t2, 0.f); t3 = fmaxf(t3, 0.f);
            }
            float2 v01 = { t0 * vf0, t1 * vf0 };
            float2 v23 = { t2 * vf1, t3 * vf1 };
            *(float2*)&out[(size_t)(r0 + r) * CD + j0 + c] = v01;
            *(float2*)&out[(size_t)(r0 + r + 8) * CD + j0 + c] = v23;
        }
}

// ---------------- launch ----------------
extern "C" void kernel_launch(void* const* d_in, const int* in_sizes, int n_in,
                              void* d_out, int out_size) {
    const float* x     = (const float*)d_in[0];
    const float* Wq    = (const float*)d_in[1];
    const float* Wk    = (const float*)d_in[2];
    const float* Wv    = (const float*)d_in[3];
    const float* ln1_g = (const float*)d_in[4];
    const float* ln1_b = (const float*)d_in[5];
    const float* fc1_w = (const float*)d_in[6];
    const float* fc1_b = (const float*)d_in[7];
    const float* fc2_w = (const float*)d_in[8];
    const float* fc2_b = (const float*)d_in[9];
    const float* ln2_g = (const float*)d_in[10];
    const float* ln2_b = (const float*)d_in[11];
    float* out = (float*)d_out;

    static float *pValid = nullptr, *pQ, *pK, *pV, *pZ, *pH, *pF, *pG;
    if (!pValid) {
        cudaGetSymbolAddress((void**)&pValid, g_valid);
        cudaGetSymbolAddress((void**)&pQ, g_Q);
        cudaGetSymbolAddress((void**)&pK, g_K);
        cudaGetSymbolAddress((void**)&pV, g_V);
        cudaGetSymbolAddress((void**)&pZ, g_Z);
        cudaGetSymbolAddress((void**)&pH, g_Hb);
        cudaGetSymbolAddress((void**)&pF, g_F);
        cudaGetSymbolAddress((void**)&pG, g_G);
    }

    k_valid<<<ROWS, 256>>>(x, pValid);
    k_qkv_mma<<<dim3(48, 32), 256>>>(x, Wq, Wk, Wv, pQ, pK, pV);
    k_flash<<<dim3(8, BH), 256>>>(pQ, pK, pV, pValid, pZ);
    k_addln<<<ROWS, 256>>>(x, pZ, ln1_g, ln1_b, pH);
    k_fc_mma<true><<<dim3(8, 32), 256>>>(pH, fc1_w, fc1_b, pValid, pF);
    k_fc_mma<false><<<dim3(8, 32), 256>>>(pF, fc2_w, fc2_b, pValid, pG);
    k_addln<<<ROWS, 256>>>(pH, pG, ln2_g, ln2_b, out);
}

// round 10
// speedup vs baseline: 1.0304x; 1.0304x over previous
#include <cuda_runtime.h>
#include <math.h>
#include <stdint.h>

// Problem dims
constexpr int CB  = 4;
constexpr int CS  = 1024;
constexpr int CD  = 1024;
constexpr int CH  = 16;
constexpr int CDK = 64;
constexpr int BH   = CB * CH;   // 64
constexpr int ROWS = CB * CS;   // 4096
constexpr float LN_EPS = 1e-5f;

// GEMM dynamic smem: 2 bufs * (128x36 A-words + 32x72/64x36 B-words) * 4B = 55296 B
constexpr int A_WORDS   = 128 * 36;          // per buffer
constexpr int B_WORDS   = 32 * 72;           // per buffer (NN 32x72 == NT 64x36)
constexpr int GEMM_SMEM = 2 * (A_WORDS + B_WORDS) * 4;

// Scratch (device globals: no cudaMalloc allowed)
__device__ float g_valid[ROWS];
__device__ float g_Q[(size_t)BH * CS * CDK];
__device__ float g_K[(size_t)BH * CS * CDK];
__device__ float g_V[(size_t)BH * CS * CDK];
__device__ float g_Z[(size_t)ROWS * CD];
__device__ float g_Hb[(size_t)ROWS * CD];
__device__ float g_F[(size_t)ROWS * CD];
__device__ float g_G[(size_t)ROWS * CD];

// ---------------- helpers ----------------
__device__ __forceinline__ float warpSum(float v) {
    #pragma unroll
    for (int o = 16; o; o >>= 1) v += __shfl_xor_sync(0xffffffffu, v, o);
    return v;
}
__device__ __forceinline__ uint32_t f2tf(float f) {
    uint32_t u;
    asm("cvt.rna.tf32.f32 %0, %1;" : "=r"(u) : "f"(f));
    return u;
}
__device__ __forceinline__ void mma8(float c[4], const uint32_t a[4], const uint32_t b[2]) {
    asm volatile(
        "mma.sync.aligned.m16n8k8.row.col.f32.tf32.tf32.f32 "
        "{%0,%1,%2,%3},{%4,%5,%6,%7},{%8,%9},{%0,%1,%2,%3};"
        : "+f"(c[0]), "+f"(c[1]), "+f"(c[2]), "+f"(c[3])
        : "r"(a[0]), "r"(a[1]), "r"(a[2]), "r"(a[3]), "r"(b[0]), "r"(b[1]));
}
__device__ __forceinline__ uint4 cvt4(float4 v) {
    uint4 u = { f2tf(v.x), f2tf(v.y), f2tf(v.z), f2tf(v.w) };
    return u;
}

// ---------------- tf32 MMA GEMM core (register-staged pipeline, dynamic smem) ----
// Block tile 128(M) x NT(N), BK=32, 256 threads = 8 warps (4 row x 2 col),
// each warp 32(M) x NT/2(N). Double-buffered smem; tile i+1 prefetched into
// registers during MMA of tile i; tf32 conversion at smem-store time.
// NN: B stored [K,N] row-major, NT must be 64. !NN: B stored [N,K] row-major.
template<bool NN, int NT>
__device__ __forceinline__ void gemm_core(const float* __restrict__ A, size_t lda,
                                          const float* __restrict__ B, size_t ldb,
                                          int K, float acc[2][NT/16][4]) {
    constexpr int NS = NT / 16;
    constexpr int PB = NN ? 2 : NT / 32;        // B prefetch float4s per thread
    extern __shared__ uint32_t dyn[];
    uint32_t* sA = dyn;                          // [buf][128][36]
    uint32_t* sB = dyn + 2 * A_WORDS;            // [buf][B_WORDS]
    const int t = threadIdx.x, lane = t & 31, w = t >> 5;
    const int wr = w >> 1, wc = w & 1;

    float4 pa[4], pb[PB];

    auto loadRegs = [&](int k0) {
        #pragma unroll
        for (int i = 0; i < 4; i++) {
            int row = (t >> 3) + (i << 5);
            int c4  = (t & 7) << 2;
            pa[i] = *(const float4*)(A + (size_t)row * lda + k0 + c4);
        }
        if (NN) {
            #pragma unroll
            for (int i = 0; i < PB; i++) {
                int k  = (t >> 4) + (i << 4);
                int n4 = (t & 15) << 2;
                pb[i] = *(const float4*)(B + (size_t)(k0 + k) * ldb + n4);
            }
        } else {
            #pragma unroll
            for (int i = 0; i < PB; i++) {
                int n  = (t >> 3) + (i << 5);
                int c4 = (t & 7) << 2;
                pb[i] = *(const float4*)(B + (size_t)n * ldb + k0 + c4);
            }
        }
    };
    auto storeSmem = [&](int buf) {
        uint32_t* a = sA + buf * A_WORDS;
        uint32_t* bp = sB + buf * B_WORDS;
        #pragma unroll
        for (int i = 0; i < 4; i++) {
            int row = (t >> 3) + (i << 5);
            int c4  = (t & 7) << 2;
            *(uint4*)&a[row * 36 + c4] = cvt4(pa[i]);
        }
        if (NN) {
            #pragma unroll
            for (int i = 0; i < PB; i++) {
                int k  = (t >> 4) + (i << 4);
                int n4 = (t & 15) << 2;
                *(uint4*)&bp[k * 72 + n4] = cvt4(pb[i]);
            }
        } else {
            #pragma unroll
            for (int i = 0; i < PB; i++) {
                int n  = (t >> 3) + (i << 5);
                int c4 = (t & 7) << 2;
                *(uint4*)&bp[n * 36 + c4] = cvt4(pb[i]);
            }
        }
    };

    const int nit = K >> 5;
    loadRegs(0);
    storeSmem(0);
    __syncthreads();
    for (int i = 0; i < nit; i++) {
        const int buf = i & 1;
        const uint32_t* a = sA + buf * A_WORDS;
        const uint32_t* bp = sB + buf * B_WORDS;
        if (i + 1 < nit) loadRegs((i + 1) << 5);

        #pragma unroll
        for (int ks = 0; ks < 32; ks += 8) {
            uint32_t af[2][4], bf[NS][2];
            #pragma unroll
            for (int ms = 0; ms < 2; ms++) {
                int r0 = wr * 32 + ms * 16 + (lane >> 2);
                int kc = ks + (lane & 3);
                af[ms][0] = a[r0 * 36 + kc];
                af[ms][1] = a[(r0 + 8) * 36 + kc];
                af[ms][2] = a[r0 * 36 + kc + 4];
                af[ms][3] = a[(r0 + 8) * 36 + kc + 4];
            }
            #pragma unroll
            for (int ns = 0; ns < NS; ns++) {
                int n0 = wc * (NT / 2) + ns * 8 + (lane >> 2);
                int kc = ks + (lane & 3);
                if (NN) {
                    bf[ns][0] = bp[kc * 72 + n0];
                    bf[ns][1] = bp[(kc + 4) * 72 + n0];
                } else {
                    bf[ns][0] = bp[n0 * 36 + kc];
                    bf[ns][1] = bp[n0 * 36 + kc + 4];
                }
            }
            #pragma unroll
            for (int ms = 0; ms < 2; ms++)
                #pragma unroll
                for (int ns = 0; ns < NS; ns++)
                    mma8(acc[ms][ns], af[ms], bf[ns]);
        }

        if (i + 1 < nit) {
            storeSmem(buf ^ 1);
            __syncthreads();
        }
    }
}

// ---------------- valid-row flags ----------------
__global__ void k_valid(const float* __restrict__ x, float* __restrict__ valid) {
    int row = blockIdx.x;
    const float* xr = x + (size_t)row * CD;
    int any = 0;
    for (int i = threadIdx.x; i < CD; i += blockDim.x) any |= (xr[i] != 0.0f);
    any = __syncthreads_or(any);
    if (threadIdx.x == 0) valid[row] = any ? 1.0f : 0.0f;
}

// ---------------- QKV projection (tf32 MMA) ----------------
__global__ void __launch_bounds__(256)
k_qkv_mma(const float* __restrict__ x,
          const float* __restrict__ Wq, const float* __restrict__ Wk,
          const float* __restrict__ Wv,
          float* __restrict__ pQ, float* __restrict__ pK, float* __restrict__ pV) {
    int nt = blockIdx.x;
    int which = nt >> 4, h = nt & 15;
    int b = blockIdx.y >> 3, s0 = (blockIdx.y & 7) << 7;
    const float* W = (which == 0 ? Wq : which == 1 ? Wk : Wv) + (size_t)h * CD * CDK;
    const float* A = x + ((size_t)b * CS + s0) * CD;
    float* out = (which == 0 ? pQ : which == 1 ? pK : pV)
                 + ((size_t)(b * 16 + h) * CS + s0) * CDK;

    float acc[2][4][4] = {};
    gemm_core<true, 64>(A, CD, W, CDK, CD, acc);

    int lane = threadIdx.x & 31, w = threadIdx.x >> 5, wr = w >> 1, wc = w & 1;
    #pragma unroll
    for (int ms = 0; ms < 2; ms++)
        #pragma unroll
        for (int ns = 0; ns < 4; ns++) {
            int r = wr * 32 + ms * 16 + (lane >> 2);
            int c = wc * 32 + ns * 8 + ((lane & 3) << 1);
            float2 v01 = { acc[ms][ns][0], acc[ms][ns][1] };
            float2 v23 = { acc[ms][ns][2], acc[ms][ns][3] };
            *(float2*)&out[(size_t)r * CDK + c] = v01;
            *(float2*)&out[(size_t)(r + 8) * CDK + c] = v23;
        }
}

// ---------------- fused flash attention ----------------
__global__ void __launch_bounds__(256)
k_flash(const float* __restrict__ pQ, const float* __restrict__ pK,
        const float* __restrict__ pV, const float* __restrict__ valid,
        float* __restrict__ pZ) {
    __shared__ uint32_t sK[64][68];
    __shared__ uint32_t sV[64][72];
    const int bh = blockIdx.y, b = bh >> 4, h = bh & 15;
    const int q0 = blockIdx.x * 128;
    const int t = threadIdx.x, lane = t & 31, w = t >> 5;
    const int rA = lane >> 2;
    const int qq = lane & 3;
    const float* vbase = valid + b * CS;

    const float* Qb = pQ + ((size_t)bh * CS + q0 + w * 16) * CDK;
    uint32_t qf[8][4];
    #pragma unroll
    for (int s = 0; s < 8; s++) {
        int k = s * 8 + qq;
        qf[s][0] = f2tf(Qb[(size_t)rA * CDK + k]);
        qf[s][1] = f2tf(Qb[(size_t)(rA + 8) * CDK + k]);
        qf[s][2] = f2tf(Qb[(size_t)rA * CDK + k + 4]);
        qf[s][3] = f2tf(Qb[(size_t)(rA + 8) * CDK + k + 4]);
    }

    float acc_o[8][4] = {};
    float mA = -INFINITY, mB = -INFINITY, lA = 0.f, lB = 0.f;

    for (int kt = 0; kt < 16; kt++) {
        __syncthreads();
        const float* Kg = pK + ((size_t)bh * CS + kt * 64) * CDK;
        const float* Vg = pV + ((size_t)bh * CS + kt * 64) * CDK;
        #pragma unroll
        for (int i = 0; i < 4; i++) {
            int row = (t >> 4) + i * 16;
            int c4  = (t & 15) << 2;
            float4 kv = *(const float4*)(Kg + (size_t)row * CDK + c4);
            float4 vv = *(const float4*)(Vg + (size_t)row * CDK + c4);
            *(uint4*)&sK[row][c4] = cvt4(kv);
            *(uint4*)&sV[row][c4] = cvt4(vv);
        }
        __syncthreads();

        float accs[8][4] = {};
        #pragma unroll
        for (int s = 0; s < 8; s++) {
            int kc = s * 8 + qq;
            #pragma unroll
            for (int j = 0; j < 8; j++) {
                int n0 = j * 8 + rA;
                uint32_t bf[2] = { sK[n0][kc], sK[n0][kc + 4] };
                mma8(accs[j], qf[s], bf);
            }
        }

        float rmaxA = -INFINITY, rmaxB = -INFINITY;
        #pragma unroll
        for (int j = 0; j < 8; j++) {
            int cg = kt * 64 + j * 8 + (qq << 1);
            float cm0 = vbase[cg], cm1 = vbase[cg + 1];
            accs[j][0] = (cm0 != 0.f) ? accs[j][0] * 0.125f : -1e30f;
            accs[j][1] = (cm1 != 0.f) ? accs[j][1] * 0.125f : -1e30f;
            accs[j][2] = (cm0 != 0.f) ? accs[j][2] * 0.125f : -1e30f;
            accs[j][3] = (cm1 != 0.f) ? accs[j][3] * 0.125f : -1e30f;
            rmaxA = fmaxf(rmaxA, fmaxf(accs[j][0], accs[j][1]));
            rmaxB = fmaxf(rmaxB, fmaxf(accs[j][2], accs[j][3]));
        }
        rmaxA = fmaxf(rmaxA, __shfl_xor_sync(~0u, rmaxA, 1));
        rmaxA = fmaxf(rmaxA, __shfl_xor_sync(~0u, rmaxA, 2));
        rmaxB = fmaxf(rmaxB, __shfl_xor_sync(~0u, rmaxB, 1));
        rmaxB = fmaxf(rmaxB, __shfl_xor_sync(~0u, rmaxB, 2));

        float mnA = fmaxf(mA, rmaxA), mnB = fmaxf(mB, rmaxB);
        float aAf = __expf(mA - mnA), aBf = __expf(mB - mnB);
        mA = mnA; mB = mnB;

        float sumA = 0.f, sumB = 0.f;
        uint32_t pt[8][4];
        #pragma unroll
        for (int j = 0; j < 8; j++) {
            float p0 = __expf(accs[j][0] - mA), p1 = __expf(accs[j][1] - mA);
            float p2 = __expf(accs[j][2] - mB), p3 = __expf(accs[j][3] - mB);
            sumA += p0 + p1; sumB += p2 + p3;
            pt[j][0] = f2tf(p0); pt[j][1] = f2tf(p1);
            pt[j][2] = f2tf(p2); pt[j][3] = f2tf(p3);
            acc_o[j][0] *= aAf; acc_o[j][1] *= aAf;
            acc_o[j][2] *= aBf; acc_o[j][3] *= aBf;
        }
        sumA += __shfl_xor_sync(~0u, sumA, 1); sumA += __shfl_xor_sync(~0u, sumA, 2);
        sumB += __shfl_xor_sync(~0u, sumB, 1); sumB += __shfl_xor_sync(~0u, sumB, 2);
        lA = lA * aAf + sumA; lB = lB * aBf + sumB;

        #pragma unroll
        for (int s = 0; s < 8; s++) {
            int src0 = (lane & ~3) | (qq >> 1);
            int src1 = src0 + 2;
            uint32_t v00 = __shfl_sync(~0u, pt[s][0], src0);
            uint32_t v01 = __shfl_sync(~0u, pt[s][1], src0);
            uint32_t v10 = __shfl_sync(~0u, pt[s][2], src0);
            uint32_t v11 = __shfl_sync(~0u, pt[s][3], src0);
            uint32_t w00 = __shfl_sync(~0u, pt[s][0], src1);
            uint32_t w01 = __shfl_sync(~0u, pt[s][1], src1);
            uint32_t w10 = __shfl_sync(~0u, pt[s][2], src1);
            uint32_t w11 = __shfl_sync(~0u, pt[s][3], src1);
            uint32_t af[4];
            af[0] = (qq & 1) ? v01 : v00;
            af[1] = (qq & 1) ? v11 : v10;
            af[2] = (qq & 1) ? w01 : w00;
            af[3] = (qq & 1) ? w11 : w10;
            int kc = s * 8 + qq;
            #pragma unroll
            for (int j = 0; j < 8; j++) {
                int n0 = j * 8 + rA;
                uint32_t bf[2] = { sV[kc][n0], sV[kc + 4][n0] };
                mma8(acc_o[j], af, bf);
            }
        }
    }

    float invA = 1.f / lA, invB = 1.f / lB;
    int qrA = q0 + w * 16 + rA, qrB = qrA + 8;
    float vfA = vbase[qrA] * invA, vfB = vbase[qrB] * invB;
    #pragma unroll
    for (int j = 0; j < 8; j++) {
        int c = j * 8 + (qq << 1);
        float2 v01 = { acc_o[j][0] * vfA, acc_o[j][1] * vfA };
        float2 v23 = { acc_o[j][2] * vfB, acc_o[j][3] * vfB };
        *(float2*)&pZ[(size_t)(b * CS + qrA) * CD + h * 64 + c] = v01;
        *(float2*)&pZ[(size_t)(b * CS + qrB) * CD + h * 64 + c] = v23;
    }
}

// ---------------- residual add + LayerNorm ----------------
__global__ void k_addln(const float* __restrict__ A, const float* __restrict__ Bv,
                        const float* __restrict__ g, const float* __restrict__ bb,
                        float* __restrict__ out) {
    int row = blockIdx.x, t = threadIdx.x;
    float4 a = ((const float4*)(A  + (size_t)row * CD))[t];
    float4 b = ((const float4*)(Bv + (size_t)row * CD))[t];
    float4 v = {a.x + b.x, a.y + b.y, a.z + b.z, a.w + b.w};
    float s = v.x + v.y + v.z + v.w;
    float q = v.x * v.x + v.y * v.y + v.z * v.z + v.w * v.w;
    __shared__ float sr1[8];
    __shared__ float sr2[8];
    s = warpSum(s); q = warpSum(q);
    if ((t & 31) == 0) { sr1[t >> 5] = s; sr2[t >> 5] = q; }
    __syncthreads();
    float S = 0.f, Q = 0.f;
    #pragma unroll
    for (int i = 0; i < 8; i++) { S += sr1[i]; Q += sr2[i]; }
    float mu = S * (1.0f / CD);
    float var = Q * (1.0f / CD) - mu * mu;
    float rs = rsqrtf(var + LN_EPS);
    float4 gg = ((const float4*)g)[t];
    float4 bv2 = ((const float4*)bb)[t];
    float4 o;
    o.x = (v.x - mu) * rs * gg.x + bv2.x;
    o.y = (v.y - mu) * rs * gg.y + bv2.y;
    o.z = (v.z - mu) * rs * gg.z + bv2.z;
    o.w = (v.w - mu) * rs * gg.w + bv2.w;
    ((float4*)(out + (size_t)row * CD))[t] = o;
}

// ---------------- FC (NT GEMM, tf32 MMA) ----------------
// grid: (16 col-tiles, 32 row-tiles)
template <bool RELU>
__global__ void __launch_bounds__(256)
k_fc_mma(const float* __restrict__ A, const float* __restrict__ W,
         const float* __restrict__ bias, const float* __restrict__ valid,
         float* __restrict__ out) {
    int j0 = blockIdx.x * 64, r0 = blockIdx.y * 128;
    float acc[2][4][4] = {};
    gemm_core<false, 64>(A + (size_t)r0 * CD, CD, W + (size_t)j0 * CD, CD, CD, acc);

    int lane = threadIdx.x & 31, w = threadIdx.x >> 5, wr = w >> 1, wc = w & 1;
    #pragma unroll
    for (int ms = 0; ms < 2; ms++)
        #pragma unroll
        for (int ns = 0; ns < 4; ns++) {
            int r = wr * 32 + ms * 16 + (lane >> 2);
            int c = wc * 32 + ns * 8 + ((lane & 3) << 1);
            float b0 = bias[j0 + c], b1 = bias[j0 + c + 1];
            float vf0 = valid[r0 + r], vf1 = valid[r0 + r + 8];
            float t0 = acc[ms][ns][0] + b0, t1 = acc[ms][ns][1] + b1;
            float t2 = acc[ms][ns][2] + b0, t3 = acc[ms][ns][3] + b1;
            if (RELU) {
                t0 = fmaxf(t0, 0.f); t1 = fmaxf(t1, 0.f);
                t2 = fmaxf(t2, 0.f); t3 = fmaxf(t3, 0.f);
            }
            float2 v01 = { t0 * vf0, t1 * vf0 };
            float2 v23 = { t2 * vf1, t3 * vf1 };
            *(float2*)&out[(size_t)(r0 + r) * CD + j0 + c] = v01;
            *(float2*)&out[(size_t)(r0 + r + 8) * CD + j0 + c] = v23;
        }
}

// ---------------- launch ----------------
extern "C" void kernel_launch(void* const* d_in, const int* in_sizes, int n_in,
                              void* d_out, int out_size) {
    const float* x     = (const float*)d_in[0];
    const float* Wq    = (const float*)d_in[1];
    const float* Wk    = (const float*)d_in[2];
    const float* Wv    = (const float*)d_in[3];
    const float* ln1_g = (const float*)d_in[4];
    const float* ln1_b = (const float*)d_in[5];
    const float* fc1_w = (const float*)d_in[6];
    const float* fc1_b = (const float*)d_in[7];
    const float* fc2_w = (const float*)d_in[8];
    const float* fc2_b = (const float*)d_in[9];
    const float* ln2_g = (const float*)d_in[10];
    const float* ln2_b = (const float*)d_in[11];
    float* out = (float*)d_out;

    static float *pValid = nullptr, *pQ, *pK, *pV, *pZ, *pH, *pF, *pG;
    if (!pValid) {
        cudaGetSymbolAddress((void**)&pValid, g_valid);
        cudaGetSymbolAddress((void**)&pQ, g_Q);
        cudaGetSymbolAddress((void**)&pK, g_K);
        cudaGetSymbolAddress((void**)&pV, g_V);
        cudaGetSymbolAddress((void**)&pZ, g_Z);
        cudaGetSymbolAddress((void**)&pH, g_Hb);
        cudaGetSymbolAddress((void**)&pF, g_F);
        cudaGetSymbolAddress((void**)&pG, g_G);
        cudaFuncSetAttribute(k_qkv_mma, cudaFuncAttributeMaxDynamicSharedMemorySize, GEMM_SMEM);
        cudaFuncSetAttribute(k_fc_mma<true>, cudaFuncAttributeMaxDynamicSharedMemorySize, GEMM_SMEM);
        cudaFuncSetAttribute(k_fc_mma<false>, cudaFuncAttributeMaxDynamicSharedMemorySize, GEMM_SMEM);
    }

    k_valid<<<ROWS, 256>>>(x, pValid);
    k_qkv_mma<<<dim3(48, 32), 256, GEMM_SMEM>>>(x, Wq, Wk, Wv, pQ, pK, pV);
    k_flash<<<dim3(8, BH), 256>>>(pQ, pK, pV, pValid, pZ);
    k_addln<<<ROWS, 256>>>(x, pZ, ln1_g, ln1_b, pH);
    k_fc_mma<true><<<dim3(16, 32), 256, GEMM_SMEM>>>(pH, fc1_w, fc1_b, pValid, pF);
    k_fc_mma<false><<<dim3(16, 32), 256, GEMM_SMEM>>>(pF, fc2_w, fc2_b, pValid, pG);
    k_addln<<<ROWS, 256>>>(pH, pG, ln2_g, ln2_b, out);
}

// round 11
// speedup vs baseline: 1.2261x; 1.1900x over previous
#include <cuda_runtime.h>
#include <cuda_fp16.h>
#include <math.h>
#include <stdint.h>

// Problem dims
constexpr int CB  = 4;
constexpr int CS  = 1024;
constexpr int CD  = 1024;
constexpr int CH  = 16;
constexpr int CDK = 64;
constexpr int BH   = CB * CH;   // 64
constexpr int ROWS = CB * CS;   // 4096
constexpr float LN_EPS = 1e-5f;

// Scratch (device globals: no cudaMalloc allowed)
__device__ float g_valid[ROWS];
__device__ float g_Q[(size_t)BH * CS * CDK];
__device__ float g_K[(size_t)BH * CS * CDK];
__device__ float g_V[(size_t)BH * CS * CDK];
__device__ float g_Z[(size_t)ROWS * CD];
__device__ float g_Hb[(size_t)ROWS * CD];
__device__ float g_F[(size_t)ROWS * CD];
__device__ float g_G[(size_t)ROWS * CD];

// ---------------- helpers ----------------
__device__ __forceinline__ float warpSum(float v) {
    #pragma unroll
    for (int o = 16; o; o >>= 1) v += __shfl_xor_sync(0xffffffffu, v, o);
    return v;
}
__device__ __forceinline__ uint32_t packh2(float lo, float hi) {
    __half2 h = __floats2half2_rn(lo, hi);
    return *reinterpret_cast<uint32_t*>(&h);
}
// m16n8k16 fp16 MMA, fp32 accumulate
__device__ __forceinline__ void mma16(float c[4], const uint32_t a[4], const uint32_t b[2]) {
    asm volatile(
        "mma.sync.aligned.m16n8k16.row.col.f32.f16.f16.f32 "
        "{%0,%1,%2,%3},{%4,%5,%6,%7},{%8,%9},{%0,%1,%2,%3};"
        : "+f"(c[0]), "+f"(c[1]), "+f"(c[2]), "+f"(c[3])
        : "r"(a[0]), "r"(a[1]), "r"(a[2]), "r"(a[3]), "r"(b[0]), "r"(b[1]));
}

// ---------------- fp16 MMA GEMM core ----------------
// Block tile 128(M) x 64(N), BK=32, 256 threads = 8 warps (4 row x 2 col),
// each warp 32(M) x 32(N). smem holds half2-packed pairs along k, row stride 20
// uint32 (16 pairs + pad). NN: B is [K,N] row-major (transposed at store).
// !NN: B is [N,K] row-major (natural packed store).
template<bool NN>
__device__ __forceinline__ void gemm_core(const float* __restrict__ A, size_t lda,
                                          const float* __restrict__ B, size_t ldb,
                                          int K, float acc[2][4][4]) {
    __shared__ uint32_t sA[128 * 20];
    __shared__ uint32_t sB[64 * 20];
    const int t = threadIdx.x, lane = t & 31, w = t >> 5;
    const int wr = w >> 1, wc = w & 1;
    const int rA = lane >> 2, qq = lane & 3;

    for (int k0 = 0; k0 < K; k0 += 32) {
        // A tile 128x32 -> packed pairs
        #pragma unroll
        for (int i = 0; i < 4; i++) {
            int idx = t + (i << 8);
            int row = idx >> 3, c4 = (idx & 7) << 2;
            float4 v = *(const float4*)(A + (size_t)row * lda + k0 + c4);
            uint2 u = { packh2(v.x, v.y), packh2(v.z, v.w) };
            *(uint2*)&sA[row * 20 + (c4 >> 1)] = u;
        }
        // B tile -> [n][k-pair]
        if (NN) {
            int k2 = t >> 4, n4 = (t & 15) << 2;
            float4 v0 = *(const float4*)(B + (size_t)(k0 + 2 * k2) * ldb + n4);
            float4 v1 = *(const float4*)(B + (size_t)(k0 + 2 * k2 + 1) * ldb + n4);
            sB[(n4 + 0) * 20 + k2] = packh2(v0.x, v1.x);
            sB[(n4 + 1) * 20 + k2] = packh2(v0.y, v1.y);
            sB[(n4 + 2) * 20 + k2] = packh2(v0.z, v1.z);
            sB[(n4 + 3) * 20 + k2] = packh2(v0.w, v1.w);
        } else {
            #pragma unroll
            for (int i = 0; i < 2; i++) {
                int idx = t + (i << 8);
                int n = idx >> 3, c4 = (idx & 7) << 2;
                float4 v = *(const float4*)(B + (size_t)n * ldb + k0 + c4);
                uint2 u = { packh2(v.x, v.y), packh2(v.z, v.w) };
                *(uint2*)&sB[n * 20 + (c4 >> 1)] = u;
            }
        }
        __syncthreads();

        #pragma unroll
        for (int ks = 0; ks < 2; ks++) {
            const int pb = (ks << 3) + qq;
            uint32_t af[2][4], bf[4][2];
            #pragma unroll
            for (int ms = 0; ms < 2; ms++) {
                int r0 = wr * 32 + ms * 16 + rA;
                af[ms][0] = sA[r0 * 20 + pb];
                af[ms][1] = sA[(r0 + 8) * 20 + pb];
                af[ms][2] = sA[r0 * 20 + pb + 4];
                af[ms][3] = sA[(r0 + 8) * 20 + pb + 4];
            }
            #pragma unroll
            for (int ns = 0; ns < 4; ns++) {
                int n0 = wc * 32 + ns * 8 + rA;
                bf[ns][0] = sB[n0 * 20 + pb];
                bf[ns][1] = sB[n0 * 20 + pb + 4];
            }
            #pragma unroll
            for (int ms = 0; ms < 2; ms++)
                #pragma unroll
                for (int ns = 0; ns < 4; ns++)
                    mma16(acc[ms][ns], af[ms], bf[ns]);
        }
        __syncthreads();
    }
}

// ---------------- valid-row flags ----------------
__global__ void k_valid(const float* __restrict__ x, float* __restrict__ valid) {
    int row = blockIdx.x;
    const float* xr = x + (size_t)row * CD;
    int any = 0;
    for (int i = threadIdx.x; i < CD; i += blockDim.x) any |= (xr[i] != 0.0f);
    any = __syncthreads_or(any);
    if (threadIdx.x == 0) valid[row] = any ? 1.0f : 0.0f;
}

// ---------------- QKV projection (fp16 MMA) ----------------
__global__ void __launch_bounds__(256)
k_qkv_mma(const float* __restrict__ x,
          const float* __restrict__ Wq, const float* __restrict__ Wk,
          const float* __restrict__ Wv,
          float* __restrict__ pQ, float* __restrict__ pK, float* __restrict__ pV) {
    int nt = blockIdx.x;
    int which = nt >> 4, h = nt & 15;
    int b = blockIdx.y >> 3, s0 = (blockIdx.y & 7) << 7;
    const float* W = (which == 0 ? Wq : which == 1 ? Wk : Wv) + (size_t)h * CD * CDK;
    const float* A = x + ((size_t)b * CS + s0) * CD;
    float* out = (which == 0 ? pQ : which == 1 ? pK : pV)
                 + ((size_t)(b * 16 + h) * CS + s0) * CDK;

    float acc[2][4][4] = {};
    gemm_core<true>(A, CD, W, CDK, CD, acc);

    int lane = threadIdx.x & 31, w = threadIdx.x >> 5, wr = w >> 1, wc = w & 1;
    #pragma unroll
    for (int ms = 0; ms < 2; ms++)
        #pragma unroll
        for (int ns = 0; ns < 4; ns++) {
            int r = wr * 32 + ms * 16 + (lane >> 2);
            int c = wc * 32 + ns * 8 + ((lane & 3) << 1);
            float2 v01 = { acc[ms][ns][0], acc[ms][ns][1] };
            float2 v23 = { acc[ms][ns][2], acc[ms][ns][3] };
            *(float2*)&out[(size_t)r * CDK + c] = v01;
            *(float2*)&out[(size_t)(r + 8) * CDK + c] = v23;
        }
}

// ---------------- fused flash attention (fp16 MMA) ----------------
// grid: (8 q-tiles, 64 bh), 256 threads = 8 warps; warp w owns q-rows 16w..16w+15.
// sK/sV: [64][36] uint32, half2-packed pairs along headdim / key dim.
__global__ void __launch_bounds__(256)
k_flash(const float* __restrict__ pQ, const float* __restrict__ pK,
        const float* __restrict__ pV, const float* __restrict__ valid,
        float* __restrict__ pZ) {
    __shared__ uint32_t sK[64 * 36];
    __shared__ uint32_t sV[64 * 36];
    const int bh = blockIdx.y, b = bh >> 4, h = bh & 15;
    const int q0 = blockIdx.x * 128;
    const int t = threadIdx.x, lane = t & 31, w = t >> 5;
    const int rA = lane >> 2;
    const int qq = lane & 3;
    const float* vbase = valid + b * CS;

    // preload Q fragments: 4 k16 tiles over headdim 64
    const float* Qb = pQ + ((size_t)bh * CS + q0 + w * 16) * CDK;
    uint32_t qf[4][4];
    #pragma unroll
    for (int s = 0; s < 4; s++) {
        int k = s * 16 + (qq << 1);
        qf[s][0] = packh2(Qb[(size_t)rA * CDK + k],       Qb[(size_t)rA * CDK + k + 1]);
        qf[s][1] = packh2(Qb[(size_t)(rA + 8) * CDK + k], Qb[(size_t)(rA + 8) * CDK + k + 1]);
        qf[s][2] = packh2(Qb[(size_t)rA * CDK + k + 8],   Qb[(size_t)rA * CDK + k + 9]);
        qf[s][3] = packh2(Qb[(size_t)(rA + 8) * CDK + k + 8], Qb[(size_t)(rA + 8) * CDK + k + 9]);
    }

    float acc_o[8][4] = {};
    float mA = -INFINITY, mB = -INFINITY, lA = 0.f, lB = 0.f;

    for (int kt = 0; kt < 16; kt++) {
        __syncthreads();
        const float* Kg = pK + ((size_t)bh * CS + kt * 64) * CDK;
        const float* Vg = pV + ((size_t)bh * CS + kt * 64) * CDK;
        // K: [64 keys][64 hd] -> sK[key][hd-pair] (natural packed store)
        #pragma unroll
        for (int i = 0; i < 4; i++) {
            int idx = t + (i << 8);
            int row = idx >> 4, c4 = (idx & 15) << 2;
            float4 kv = *(const float4*)(Kg + (size_t)row * CDK + c4);
            uint2 u = { packh2(kv.x, kv.y), packh2(kv.z, kv.w) };
            *(uint2*)&sK[row * 36 + (c4 >> 1)] = u;
        }
        // V: [64 keys][64 hd] -> sV[hd][key-pair] (transposed packed store)
        #pragma unroll
        for (int i = 0; i < 2; i++) {
            int k2 = (t >> 4) + (i << 4);     // key-pair index 0..31
            int n4 = (t & 15) << 2;           // headdim cols
            float4 v0 = *(const float4*)(Vg + (size_t)(2 * k2) * CDK + n4);
            float4 v1 = *(const float4*)(Vg + (size_t)(2 * k2 + 1) * CDK + n4);
            sV[(n4 + 0) * 36 + k2] = packh2(v0.x, v1.x);
            sV[(n4 + 1) * 36 + k2] = packh2(v0.y, v1.y);
            sV[(n4 + 2) * 36 + k2] = packh2(v0.z, v1.z);
            sV[(n4 + 3) * 36 + k2] = packh2(v0.w, v1.w);
        }
        __syncthreads();

        // S = Q K^T : 4 k16 tiles x 8 n-blocks
        float accs[8][4] = {};
        #pragma unroll
        for (int s = 0; s < 4; s++) {
            const int pb = (s << 3) + qq;
            #pragma unroll
            for (int j = 0; j < 8; j++) {
                int n0 = j * 8 + rA;
                uint32_t bf[2] = { sK[n0 * 36 + pb], sK[n0 * 36 + pb + 4] };
                mma16(accs[j], qf[s], bf);
            }
        }

        // mask + scale, row max (accumulator cols 2q, 2q+1 per block)
        float rmaxA = -INFINITY, rmaxB = -INFINITY;
        #pragma unroll
        for (int j = 0; j < 8; j++) {
            int cg = kt * 64 + j * 8 + (qq << 1);
            float cm0 = vbase[cg], cm1 = vbase[cg + 1];
            accs[j][0] = (cm0 != 0.f) ? accs[j][0] * 0.125f : -1e30f;
            accs[j][1] = (cm1 != 0.f) ? accs[j][1] * 0.125f : -1e30f;
            accs[j][2] = (cm0 != 0.f) ? accs[j][2] * 0.125f : -1e30f;
            accs[j][3] = (cm1 != 0.f) ? accs[j][3] * 0.125f : -1e30f;
            rmaxA = fmaxf(rmaxA, fmaxf(accs[j][0], accs[j][1]));
            rmaxB = fmaxf(rmaxB, fmaxf(accs[j][2], accs[j][3]));
        }
        rmaxA = fmaxf(rmaxA, __shfl_xor_sync(~0u, rmaxA, 1));
        rmaxA = fmaxf(rmaxA, __shfl_xor_sync(~0u, rmaxA, 2));
        rmaxB = fmaxf(rmaxB, __shfl_xor_sync(~0u, rmaxB, 1));
        rmaxB = fmaxf(rmaxB, __shfl_xor_sync(~0u, rmaxB, 2));

        float mnA = fmaxf(mA, rmaxA), mnB = fmaxf(mB, rmaxB);
        float aAf = __expf(mA - mnA), aBf = __expf(mB - mnB);
        mA = mnA; mB = mnB;

        // exp + pack P directly into fp16 A-fragment form (no shuffles needed)
        float sumA = 0.f, sumB = 0.f;
        uint32_t pt2[8][2];
        #pragma unroll
        for (int j = 0; j < 8; j++) {
            float p0 = __expf(accs[j][0] - mA), p1 = __expf(accs[j][1] - mA);
            float p2 = __expf(accs[j][2] - mB), p3 = __expf(accs[j][3] - mB);
            sumA += p0 + p1; sumB += p2 + p3;
            pt2[j][0] = packh2(p0, p1);      // P[r  ][2q..2q+1] of block j
            pt2[j][1] = packh2(p2, p3);      // P[r+8][2q..2q+1] of block j
            acc_o[j][0] *= aAf; acc_o[j][1] *= aAf;
            acc_o[j][2] *= aBf; acc_o[j][3] *= aBf;
        }
        sumA += __shfl_xor_sync(~0u, sumA, 1); sumA += __shfl_xor_sync(~0u, sumA, 2);
        sumB += __shfl_xor_sync(~0u, sumB, 1); sumB += __shfl_xor_sync(~0u, sumB, 2);
        lA = lA * aAf + sumA; lB = lB * aBf + sumB;

        // O += P V : 4 k16 tiles (keys), A-frags straight from pt2
        #pragma unroll
        for (int kb = 0; kb < 4; kb++) {
            uint32_t af[4] = { pt2[2 * kb][0], pt2[2 * kb][1],
                               pt2[2 * kb + 1][0], pt2[2 * kb + 1][1] };
            const int pb = (kb << 3) + qq;
            #pragma unroll
            for (int j = 0; j < 8; j++) {
                int n0 = j * 8 + rA;
                uint32_t bf[2] = { sV[n0 * 36 + pb], sV[n0 * 36 + pb + 4] };
                mma16(acc_o[j], af, bf);
            }
        }
    }

    // epilogue: normalize, q-row mask, write Z[b,s,d]
    float invA = 1.f / lA, invB = 1.f / lB;
    int qrA = q0 + w * 16 + rA, qrB = qrA + 8;
    float vfA = vbase[qrA] * invA, vfB = vbase[qrB] * invB;
    #pragma unroll
    for (int j = 0; j < 8; j++) {
        int c = j * 8 + (qq << 1);
        float2 v01 = { acc_o[j][0] * vfA, acc_o[j][1] * vfA };
        float2 v23 = { acc_o[j][2] * vfB, acc_o[j][3] * vfB };
        *(float2*)&pZ[(size_t)(b * CS + qrA) * CD + h * 64 + c] = v01;
        *(float2*)&pZ[(size_t)(b * CS + qrB) * CD + h * 64 + c] = v23;
    }
}

// ---------------- residual add + LayerNorm ----------------
__global__ void k_addln(const float* __restrict__ A, const float* __restrict__ Bv,
                        const float* __restrict__ g, const float* __restrict__ bb,
                        float* __restrict__ out) {
    int row = blockIdx.x, t = threadIdx.x;
    float4 a = ((const float4*)(A  + (size_t)row * CD))[t];
    float4 b = ((const float4*)(Bv + (size_t)row * CD))[t];
    float4 v = {a.x + b.x, a.y + b.y, a.z + b.z, a.w + b.w};
    float s = v.x + v.y + v.z + v.w;
    float q = v.x * v.x + v.y * v.y + v.z * v.z + v.w * v.w;
    __shared__ float sr1[8];
    __shared__ float sr2[8];
    s = warpSum(s); q = warpSum(q);
    if ((t & 31) == 0) { sr1[t >> 5] = s; sr2[t >> 5] = q; }
    __syncthreads();
    float S = 0.f, Q = 0.f;
    #pragma unroll
    for (int i = 0; i < 8; i++) { S += sr1[i]; Q += sr2[i]; }
    float mu = S * (1.0f / CD);
    float var = Q * (1.0f / CD) - mu * mu;
    float rs = rsqrtf(var + LN_EPS);
    float4 gg = ((const float4*)g)[t];
    float4 bv2 = ((const float4*)bb)[t];
    float4 o;
    o.x = (v.x - mu) * rs * gg.x + bv2.x;
    o.y = (v.y - mu) * rs * gg.y + bv2.y;
    o.z = (v.z - mu) * rs * gg.z + bv2.z;
    o.w = (v.w - mu) * rs * gg.w + bv2.w;
    ((float4*)(out + (size_t)row * CD))[t] = o;
}

// ---------------- FC (NT GEMM, fp16 MMA) ----------------
// grid: (16 col-tiles, 32 row-tiles)
template <bool RELU>
__global__ void __launch_bounds__(256)
k_fc_mma(const float* __restrict__ A, const float* __restrict__ W,
         const float* __restrict__ bias, const float* __restrict__ valid,
         float* __restrict__ out) {
    int j0 = blockIdx.x * 64, r0 = blockIdx.y * 128;
    float acc[2][4][4] = {};
    gemm_core<false>(A + (size_t)r0 * CD, CD, W + (size_t)j0 * CD, CD, CD, acc);

    int lane = threadIdx.x & 31, w = threadIdx.x >> 5, wr = w >> 1, wc = w & 1;
    #pragma unroll
    for (int ms = 0; ms < 2; ms++)
        #pragma unroll
        for (int ns = 0; ns < 4; ns++) {
            int r = wr * 32 + ms * 16 + (lane >> 2);
            int c = wc * 32 + ns * 8 + ((lane & 3) << 1);
            float b0 = bias[j0 + c], b1 = bias[j0 + c + 1];
            float vf0 = valid[r0 + r], vf1 = valid[r0 + r + 8];
            float t0 = acc[ms][ns][0] + b0, t1 = acc[ms][ns][1] + b1;
            float t2 = acc[ms][ns][2] + b0, t3 = acc[ms][ns][3] + b1;
            if (RELU) {
                t0 = fmaxf(t0, 0.f); t1 = fmaxf(t1, 0.f);
                t2 = fmaxf(t2, 0.f); t3 = fmaxf(t3, 0.f);
            }
            float2 v01 = { t0 * vf0, t1 * vf0 };
            float2 v23 = { t2 * vf1, t3 * vf1 };
            *(float2*)&out[(size_t)(r0 + r) * CD + j0 + c] = v01;
            *(float2*)&out[(size_t)(r0 + r + 8) * CD + j0 + c] = v23;
        }
}

// ---------------- launch ----------------
extern "C" void kernel_launch(void* const* d_in, const int* in_sizes, int n_in,
                              void* d_out, int out_size) {
    const float* x     = (const float*)d_in[0];
    const float* Wq    = (const float*)d_in[1];
    const float* Wk    = (const float*)d_in[2];
    const float* Wv    = (const float*)d_in[3];
    const float* ln1_g = (const float*)d_in[4];
    const float* ln1_b = (const float*)d_in[5];
    const float* fc1_w = (const float*)d_in[6];
    const float* fc1_b = (const float*)d_in[7];
    const float* fc2_w = (const float*)d_in[8];
    const float* fc2_b = (const float*)d_in[9];
    const float* ln2_g = (const float*)d_in[10];
    const float* ln2_b = (const float*)d_in[11];
    float* out = (float*)d_out;

    static float *pValid = nullptr, *pQ, *pK, *pV, *pZ, *pH, *pF, *pG;
    if (!pValid) {
        cudaGetSymbolAddress((void**)&pValid, g_valid);
        cudaGetSymbolAddress((void**)&pQ, g_Q);
        cudaGetSymbolAddress((void**)&pK, g_K);
        cudaGetSymbolAddress((void**)&pV, g_V);
        cudaGetSymbolAddress((void**)&pZ, g_Z);
        cudaGetSymbolAddress((void**)&pH, g_Hb);
        cudaGetSymbolAddress((void**)&pF, g_F);
        cudaGetSymbolAddress((void**)&pG, g_G);
    }

    k_valid<<<ROWS, 256>>>(x, pValid);
    k_qkv_mma<<<dim3(48, 32), 256>>>(x, Wq, Wk, Wv, pQ, pK, pV);
    k_flash<<<dim3(8, BH), 256>>>(pQ, pK, pV, pValid, pZ);
    k_addln<<<ROWS, 256>>>(x, pZ, ln1_g, ln1_b, pH);
    k_fc_mma<true><<<dim3(16, 32), 256>>>(pH, fc1_w, fc1_b, pValid, pF);
    k_fc_mma<false><<<dim3(16, 32), 256>>>(pF, fc2_w, fc2_b, pValid, pG);
    k_addln<<<ROWS, 256>>>(pH, pG, ln2_g, ln2_b, out);
}

// round 12
// speedup vs baseline: 1.3195x; 1.0762x over previous
#include <cuda_runtime.h>
#include <cuda_fp16.h>
#include <math.h>
#include <stdint.h>

// Problem dims
constexpr int CB  = 4;
constexpr int CS  = 1024;
constexpr int CD  = 1024;
constexpr int CH  = 16;
constexpr int CDK = 64;
constexpr int BH   = CB * CH;   // 64
constexpr int ROWS = CB * CS;   // 4096
constexpr float LN_EPS = 1e-5f;

// Scratch (device globals: no cudaMalloc allowed)
__device__ float g_valid[ROWS];
__device__ float g_Q[(size_t)BH * CS * CDK];
__device__ float g_K[(size_t)BH * CS * CDK];
__device__ float g_V[(size_t)BH * CS * CDK];
__device__ float g_Z[(size_t)ROWS * CD];
__device__ float g_Hb[(size_t)ROWS * CD];
__device__ float g_G[(size_t)ROWS * CD];
// fp16 mirrors
__device__ __half g_xh[(size_t)ROWS * CD];
__device__ __half g_Wqh[(size_t)CH * CD * CDK];
__device__ __half g_Wkh[(size_t)CH * CD * CDK];
__device__ __half g_Wvh[(size_t)CH * CD * CDK];
__device__ __half g_W1h[(size_t)CD * CD];
__device__ __half g_W2h[(size_t)CD * CD];
__device__ __half g_Hh[(size_t)ROWS * CD];
__device__ __half g_Fh[(size_t)ROWS * CD];

// ---------------- helpers ----------------
__device__ __forceinline__ float warpSum(float v) {
    #pragma unroll
    for (int o = 16; o; o >>= 1) v += __shfl_xor_sync(0xffffffffu, v, o);
    return v;
}
__device__ __forceinline__ uint32_t packh2(float lo, float hi) {
    __half2 h = __floats2half2_rn(lo, hi);
    return *reinterpret_cast<uint32_t*>(&h);
}
__device__ __forceinline__ void mma16(float c[4], const uint32_t a[4], const uint32_t b[2]) {
    asm volatile(
        "mma.sync.aligned.m16n8k16.row.col.f32.f16.f16.f32 "
        "{%0,%1,%2,%3},{%4,%5,%6,%7},{%8,%9},{%0,%1,%2,%3};"
        : "+f"(c[0]), "+f"(c[1]), "+f"(c[2]), "+f"(c[3])
        : "r"(a[0]), "r"(a[1]), "r"(a[2]), "r"(a[3]), "r"(b[0]), "r"(b[1]));
}

// ---------------- fp32 -> fp16 convert (grid-stride-free, n % 1024 == 0) ----------
__global__ void k_cvt(const float* __restrict__ s, __half* __restrict__ d) {
    int i = blockIdx.x * 256 + threadIdx.x;
    float4 v = ((const float4*)s)[i];
    uint2 u = { packh2(v.x, v.y), packh2(v.z, v.w) };
    ((uint2*)d)[i] = u;
}

// ---------------- fp16-input MMA GEMM core, 128x128 tile ----------------
// BK=32, 256 threads = 8 warps (4 row x 2 col); warp tile 32(M) x 64(N).
// smem rows hold 16 half2 pairs along k, stride 20 words (conflict-free).
// NN (QKV): B is W[head][k][64] with 2 heads per tile -> transpose pack via byte_perm.
// !NN (FC): B[n][k] row-major (natural packed pairs).
template<bool NN>
__device__ __forceinline__ void gemm16(const __half* __restrict__ A, int lda,
                                       const __half* __restrict__ B, int ldb,
                                       float acc[2][8][4]) {
    __shared__ uint32_t sA[128 * 20];
    __shared__ uint32_t sB[128 * 20];
    const int t = threadIdx.x, lane = t & 31, w = t >> 5;
    const int wr = w >> 1, wc = w & 1;
    const int rA = lane >> 2, qq = lane & 3;

    for (int k0 = 0; k0 < CD; k0 += 32) {
        // A tile 128x32 halves (pairs along k are natural)
        #pragma unroll
        for (int i = 0; i < 2; i++) {
            int idx = t + (i << 8);
            int row = idx >> 2, c8 = (idx & 3) << 3;
            *(uint4*)&sA[row * 20 + (c8 >> 1)] =
                *(const uint4*)(A + (size_t)row * lda + k0 + c8);
        }
        if (NN) {
            // B: rows k, cols n (2 heads x 64) -> sB[n][k-pair] via byte_perm transpose
            #pragma unroll
            for (int i = 0; i < 2; i++) {
                int k2 = t & 15;
                int g  = (t >> 4) + (i << 4);   // 0..31
                int n4 = g << 2;
                const __half* bb = B + ((n4 >> 6) ? (CD * CDK) : 0)
                                     + (size_t)(k0 + 2 * k2) * CDK + (n4 & 63);
                uint2 v0 = *(const uint2*)bb;
                uint2 v1 = *(const uint2*)(bb + CDK);
                sB[(n4 + 0) * 20 + k2] = __byte_perm(v0.x, v1.x, 0x5410);
                sB[(n4 + 1) * 20 + k2] = __byte_perm(v0.x, v1.x, 0x7632);
                sB[(n4 + 2) * 20 + k2] = __byte_perm(v0.y, v1.y, 0x5410);
                sB[(n4 + 3) * 20 + k2] = __byte_perm(v0.y, v1.y, 0x7632);
            }
        } else {
            #pragma unroll
            for (int i = 0; i < 2; i++) {
                int idx = t + (i << 8);
                int n = idx >> 2, c8 = (idx & 3) << 3;
                *(uint4*)&sB[n * 20 + (c8 >> 1)] =
                    *(const uint4*)(B + (size_t)n * ldb + k0 + c8);
            }
        }
        __syncthreads();

        #pragma unroll
        for (int ks = 0; ks < 2; ks++) {
            const int pb = (ks << 3) + qq;
            uint32_t af[2][4], bf[8][2];
            #pragma unroll
            for (int ms = 0; ms < 2; ms++) {
                int r0 = wr * 32 + ms * 16 + rA;
                af[ms][0] = sA[r0 * 20 + pb];
                af[ms][1] = sA[(r0 + 8) * 20 + pb];
                af[ms][2] = sA[r0 * 20 + pb + 4];
                af[ms][3] = sA[(r0 + 8) * 20 + pb + 4];
            }
            #pragma unroll
            for (int ns = 0; ns < 8; ns++) {
                int n0 = wc * 64 + ns * 8 + rA;
                bf[ns][0] = sB[n0 * 20 + pb];
                bf[ns][1] = sB[n0 * 20 + pb + 4];
            }
            #pragma unroll
            for (int ms = 0; ms < 2; ms++)
                #pragma unroll
                for (int ns = 0; ns < 8; ns++)
                    mma16(acc[ms][ns], af[ms], bf[ns]);
        }
        __syncthreads();
    }
}

// ---------------- valid-row flags ----------------
__global__ void k_valid(const float* __restrict__ x, float* __restrict__ valid) {
    int row = blockIdx.x;
    const float* xr = x + (size_t)row * CD;
    int any = 0;
    for (int i = threadIdx.x; i < CD; i += blockDim.x) any |= (xr[i] != 0.0f);
    any = __syncthreads_or(any);
    if (threadIdx.x == 0) valid[row] = any ? 1.0f : 0.0f;
}

// ---------------- QKV projection (fp16 in, fp32 out), 2 heads per tile ----------
// grid: (24 = 3 which x 8 head-pairs, 32 row tiles)
__global__ void __launch_bounds__(256)
k_qkv16(const __half* __restrict__ xh,
        const __half* __restrict__ Wqh, const __half* __restrict__ Wkh,
        const __half* __restrict__ Wvh,
        float* __restrict__ pQ, float* __restrict__ pK, float* __restrict__ pV) {
    int which = blockIdx.x >> 3, hp = blockIdx.x & 7;
    int b = blockIdx.y >> 3, s0 = (blockIdx.y & 7) << 7;
    const __half* W = (which == 0 ? Wqh : which == 1 ? Wkh : Wvh)
                      + (size_t)hp * 2 * CD * CDK;
    const __half* A = xh + ((size_t)b * CS + s0) * CD;
    float* P = (which == 0 ? pQ : which == 1 ? pK : pV);

    float acc[2][8][4] = {};
    gemm16<true>(A, CD, W, CDK, acc);

    int lane = threadIdx.x & 31, w = threadIdx.x >> 5, wr = w >> 1, wc = w & 1;
    int head = hp * 2 + wc;
    float* out = P + ((size_t)(b * 16 + head) * CS + s0) * CDK;
    #pragma unroll
    for (int ms = 0; ms < 2; ms++)
        #pragma unroll
        for (int ns = 0; ns < 8; ns++) {
            int r = wr * 32 + ms * 16 + (lane >> 2);
            int e = ns * 8 + ((lane & 3) << 1);
            float2 v01 = { acc[ms][ns][0], acc[ms][ns][1] };
            float2 v23 = { acc[ms][ns][2], acc[ms][ns][3] };
            *(float2*)&out[(size_t)r * CDK + e] = v01;
            *(float2*)&out[(size_t)(r + 8) * CDK + e] = v23;
        }
}

// ---------------- fused flash attention (fp16 MMA; identical to round 11) -------
__global__ void __launch_bounds__(256)
k_flash(const float* __restrict__ pQ, const float* __restrict__ pK,
        const float* __restrict__ pV, const float* __restrict__ valid,
        float* __restrict__ pZ) {
    __shared__ uint32_t sK[64 * 36];
    __shared__ uint32_t sV[64 * 36];
    const int bh = blockIdx.y, b = bh >> 4, h = bh & 15;
    const int q0 = blockIdx.x * 128;
    const int t = threadIdx.x, lane = t & 31, w = t >> 5;
    const int rA = lane >> 2;
    const int qq = lane & 3;
    const float* vbase = valid + b * CS;

    const float* Qb = pQ + ((size_t)bh * CS + q0 + w * 16) * CDK;
    uint32_t qf[4][4];
    #pragma unroll
    for (int s = 0; s < 4; s++) {
        int k = s * 16 + (qq << 1);
        qf[s][0] = packh2(Qb[(size_t)rA * CDK + k],       Qb[(size_t)rA * CDK + k + 1]);
        qf[s][1] = packh2(Qb[(size_t)(rA + 8) * CDK + k], Qb[(size_t)(rA + 8) * CDK + k + 1]);
        qf[s][2] = packh2(Qb[(size_t)rA * CDK + k + 8],   Qb[(size_t)rA * CDK + k + 9]);
        qf[s][3] = packh2(Qb[(size_t)(rA + 8) * CDK + k + 8], Qb[(size_t)(rA + 8) * CDK + k + 9]);
    }

    float acc_o[8][4] = {};
    float mA = -INFINITY, mB = -INFINITY, lA = 0.f, lB = 0.f;

    for (int kt = 0; kt < 16; kt++) {
        __syncthreads();
        const float* Kg = pK + ((size_t)bh * CS + kt * 64) * CDK;
        const float* Vg = pV + ((size_t)bh * CS + kt * 64) * CDK;
        #pragma unroll
        for (int i = 0; i < 4; i++) {
            int idx = t + (i << 8);
            int row = idx >> 4, c4 = (idx & 15) << 2;
            float4 kv = *(const float4*)(Kg + (size_t)row * CDK + c4);
            uint2 u = { packh2(kv.x, kv.y), packh2(kv.z, kv.w) };
            *(uint2*)&sK[row * 36 + (c4 >> 1)] = u;
        }
        #pragma unroll
        for (int i = 0; i < 2; i++) {
            int k2 = (t >> 4) + (i << 4);
            int n4 = (t & 15) << 2;
            float4 v0 = *(const float4*)(Vg + (size_t)(2 * k2) * CDK + n4);
            float4 v1 = *(const float4*)(Vg + (size_t)(2 * k2 + 1) * CDK + n4);
            sV[(n4 + 0) * 36 + k2] = packh2(v0.x, v1.x);
            sV[(n4 + 1) * 36 + k2] = packh2(v0.y, v1.y);
            sV[(n4 + 2) * 36 + k2] = packh2(v0.z, v1.z);
            sV[(n4 + 3) * 36 + k2] = packh2(v0.w, v1.w);
        }
        __syncthreads();

        float accs[8][4] = {};
        #pragma unroll
        for (int s = 0; s < 4; s++) {
            const int pb = (s << 3) + qq;
            #pragma unroll
            for (int j = 0; j < 8; j++) {
                int n0 = j * 8 + rA;
                uint32_t bf[2] = { sK[n0 * 36 + pb], sK[n0 * 36 + pb + 4] };
                mma16(accs[j], qf[s], bf);
            }
        }

        float rmaxA = -INFINITY, rmaxB = -INFINITY;
        #pragma unroll
        for (int j = 0; j < 8; j++) {
            int cg = kt * 64 + j * 8 + (qq << 1);
            float cm0 = vbase[cg], cm1 = vbase[cg + 1];
            accs[j][0] = (cm0 != 0.f) ? accs[j][0] * 0.125f : -1e30f;
            accs[j][1] = (cm1 != 0.f) ? accs[j][1] * 0.125f : -1e30f;
            accs[j][2] = (cm0 != 0.f) ? accs[j][2] * 0.125f : -1e30f;
            accs[j][3] = (cm1 != 0.f) ? accs[j][3] * 0.125f : -1e30f;
            rmaxA = fmaxf(rmaxA, fmaxf(accs[j][0], accs[j][1]));
            rmaxB = fmaxf(rmaxB, fmaxf(accs[j][2], accs[j][3]));
        }
        rmaxA = fmaxf(rmaxA, __shfl_xor_sync(~0u, rmaxA, 1));
        rmaxA = fmaxf(rmaxA, __shfl_xor_sync(~0u, rmaxA, 2));
        rmaxB = fmaxf(rmaxB, __shfl_xor_sync(~0u, rmaxB, 1));
        rmaxB = fmaxf(rmaxB, __shfl_xor_sync(~0u, rmaxB, 2));

        float mnA = fmaxf(mA, rmaxA), mnB = fmaxf(mB, rmaxB);
        float aAf = __expf(mA - mnA), aBf = __expf(mB - mnB);
        mA = mnA; mB = mnB;

        float sumA = 0.f, sumB = 0.f;
        uint32_t pt2[8][2];
        #pragma unroll
        for (int j = 0; j < 8; j++) {
            float p0 = __expf(accs[j][0] - mA), p1 = __expf(accs[j][1] - mA);
            float p2 = __expf(accs[j][2] - mB), p3 = __expf(accs[j][3] - mB);
            sumA += p0 + p1; sumB += p2 + p3;
            pt2[j][0] = packh2(p0, p1);
            pt2[j][1] = packh2(p2, p3);
            acc_o[j][0] *= aAf; acc_o[j][1] *= aAf;
            acc_o[j][2] *= aBf; acc_o[j][3] *= aBf;
        }
        sumA += __shfl_xor_sync(~0u, sumA, 1); sumA += __shfl_xor_sync(~0u, sumA, 2);
        sumB += __shfl_xor_sync(~0u, sumB, 1); sumB += __shfl_xor_sync(~0u, sumB, 2);
        lA = lA * aAf + sumA; lB = lB * aBf + sumB;

        #pragma unroll
        for (int kb = 0; kb < 4; kb++) {
            uint32_t af[4] = { pt2[2 * kb][0], pt2[2 * kb][1],
                               pt2[2 * kb + 1][0], pt2[2 * kb + 1][1] };
            const int pb = (kb << 3) + qq;
            #pragma unroll
            for (int j = 0; j < 8; j++) {
                int n0 = j * 8 + rA;
                uint32_t bf[2] = { sV[n0 * 36 + pb], sV[n0 * 36 + pb + 4] };
                mma16(acc_o[j], af, bf);
            }
        }
    }

    float invA = 1.f / lA, invB = 1.f / lB;
    int qrA = q0 + w * 16 + rA, qrB = qrA + 8;
    float vfA = vbase[qrA] * invA, vfB = vbase[qrB] * invB;
    #pragma unroll
    for (int j = 0; j < 8; j++) {
        int c = j * 8 + (qq << 1);
        float2 v01 = { acc_o[j][0] * vfA, acc_o[j][1] * vfA };
        float2 v23 = { acc_o[j][2] * vfB, acc_o[j][3] * vfB };
        *(float2*)&pZ[(size_t)(b * CS + qrA) * CD + h * 64 + c] = v01;
        *(float2*)&pZ[(size_t)(b * CS + qrB) * CD + h * 64 + c] = v23;
    }
}

// ---------------- residual add + LayerNorm (optional fp16 mirror) ---------------
template<bool H16>
__global__ void k_addln(const float* __restrict__ A, const float* __restrict__ Bv,
                        const float* __restrict__ g, const float* __restrict__ bb,
                        float* __restrict__ out, __half* __restrict__ outh) {
    int row = blockIdx.x, t = threadIdx.x;
    float4 a = ((const float4*)(A  + (size_t)row * CD))[t];
    float4 b = ((const float4*)(Bv + (size_t)row * CD))[t];
    float4 v = {a.x + b.x, a.y + b.y, a.z + b.z, a.w + b.w};
    float s = v.x + v.y + v.z + v.w;
    float q = v.x * v.x + v.y * v.y + v.z * v.z + v.w * v.w;
    __shared__ float sr1[8];
    __shared__ float sr2[8];
    s = warpSum(s); q = warpSum(q);
    if ((t & 31) == 0) { sr1[t >> 5] = s; sr2[t >> 5] = q; }
    __syncthreads();
    float S = 0.f, Q = 0.f;
    #pragma unroll
    for (int i = 0; i < 8; i++) { S += sr1[i]; Q += sr2[i]; }
    float mu = S * (1.0f / CD);
    float var = Q * (1.0f / CD) - mu * mu;
    float rs = rsqrtf(var + LN_EPS);
    float4 gg = ((const float4*)g)[t];
    float4 bv2 = ((const float4*)bb)[t];
    float4 o;
    o.x = (v.x - mu) * rs * gg.x + bv2.x;
    o.y = (v.y - mu) * rs * gg.y + bv2.y;
    o.z = (v.z - mu) * rs * gg.z + bv2.z;
    o.w = (v.w - mu) * rs * gg.w + bv2.w;
    ((float4*)(out + (size_t)row * CD))[t] = o;
    if (H16) {
        uint2 u = { packh2(o.x, o.y), packh2(o.z, o.w) };
        ((uint2*)(outh + (size_t)row * CD))[t] = u;
    }
}

// ---------------- FC1: fp16 in -> relu*valid -> fp16 out ----------------
// grid: (8 col-tiles, 32 row-tiles)
__global__ void __launch_bounds__(256)
k_fc1(const __half* __restrict__ A, const __half* __restrict__ W,
      const float* __restrict__ bias, const float* __restrict__ valid,
      __half* __restrict__ outh) {
    int j0 = blockIdx.x * 128, r0 = blockIdx.y * 128;
    float acc[2][8][4] = {};
    gemm16<false>(A + (size_t)r0 * CD, CD, W + (size_t)j0 * CD, CD, acc);

    int lane = threadIdx.x & 31, w = threadIdx.x >> 5, wr = w >> 1, wc = w & 1;
    #pragma unroll
    for (int ms = 0; ms < 2; ms++)
        #pragma unroll
        for (int ns = 0; ns < 8; ns++) {
            int r = wr * 32 + ms * 16 + (lane >> 2);
            int c = wc * 64 + ns * 8 + ((lane & 3) << 1);
            float b0 = bias[j0 + c], b1 = bias[j0 + c + 1];
            float vf0 = valid[r0 + r], vf1 = valid[r0 + r + 8];
            float t0 = fmaxf(acc[ms][ns][0] + b0, 0.f) * vf0;
            float t1 = fmaxf(acc[ms][ns][1] + b1, 0.f) * vf0;
            float t2 = fmaxf(acc[ms][ns][2] + b0, 0.f) * vf1;
            float t3 = fmaxf(acc[ms][ns][3] + b1, 0.f) * vf1;
            *(uint32_t*)&outh[(size_t)(r0 + r) * CD + j0 + c]     = packh2(t0, t1);
            *(uint32_t*)&outh[(size_t)(r0 + r + 8) * CD + j0 + c] = packh2(t2, t3);
        }
}

// ---------------- FC2: fp16 in -> +bias, *valid -> fp32 out ----------------
__global__ void __launch_bounds__(256)
k_fc2(const __half* __restrict__ A, const __half* __restrict__ W,
      const float* __restrict__ bias, const float* __restrict__ valid,
      float* __restrict__ out) {
    int j0 = blockIdx.x * 128, r0 = blockIdx.y * 128;
    float acc[2][8][4] = {};
    gemm16<false>(A + (size_t)r0 * CD, CD, W + (size_t)j0 * CD, CD, acc);

    int lane = threadIdx.x & 31, w = threadIdx.x >> 5, wr = w >> 1, wc = w & 1;
    #pragma unroll
    for (int ms = 0; ms < 2; ms++)
        #pragma unroll
        for (int ns = 0; ns < 8; ns++) {
            int r = wr * 32 + ms * 16 + (lane >> 2);
            int c = wc * 64 + ns * 8 + ((lane & 3) << 1);
            float b0 = bias[j0 + c], b1 = bias[j0 + c + 1];
            float vf0 = valid[r0 + r], vf1 = valid[r0 + r + 8];
            float2 v01 = { (acc[ms][ns][0] + b0) * vf0, (acc[ms][ns][1] + b1) * vf0 };
            float2 v23 = { (acc[ms][ns][2] + b0) * vf1, (acc[ms][ns][3] + b1) * vf1 };
            *(float2*)&out[(size_t)(r0 + r) * CD + j0 + c] = v01;
            *(float2*)&out[(size_t)(r0 + r + 8) * CD + j0 + c] = v23;
        }
}

// ---------------- launch ----------------
extern "C" void kernel_launch(void* const* d_in, const int* in_sizes, int n_in,
                              void* d_out, int out_size) {
    const float* x     = (const float*)d_in[0];
    const float* Wq    = (const float*)d_in[1];
    const float* Wk    = (const float*)d_in[2];
    const float* Wv    = (const float*)d_in[3];
    const float* ln1_g = (const float*)d_in[4];
    const float* ln1_b = (const float*)d_in[5];
    const float* fc1_w = (const float*)d_in[6];
    const float* fc1_b = (const float*)d_in[7];
    const float* fc2_w = (const float*)d_in[8];
    const float* fc2_b = (const float*)d_in[9];
    const float* ln2_g = (const float*)d_in[10];
    const float* ln2_b = (const float*)d_in[11];
    float* out = (float*)d_out;

    static float *pValid = nullptr, *pQ, *pK, *pV, *pZ, *pH, *pG;
    static __half *pXh, *pWqh, *pWkh, *pWvh, *pW1h, *pW2h, *pHh, *pFh;
    if (!pValid) {
        cudaGetSymbolAddress((void**)&pValid, g_valid);
        cudaGetSymbolAddress((void**)&pQ, g_Q);
        cudaGetSymbolAddress((void**)&pK, g_K);
        cudaGetSymbolAddress((void**)&pV, g_V);
        cudaGetSymbolAddress((void**)&pZ, g_Z);
        cudaGetSymbolAddress((void**)&pH, g_Hb);
        cudaGetSymbolAddress((void**)&pG, g_G);
        cudaGetSymbolAddress((void**)&pXh, g_xh);
        cudaGetSymbolAddress((void**)&pWqh, g_Wqh);
        cudaGetSymbolAddress((void**)&pWkh, g_Wkh);
        cudaGetSymbolAddress((void**)&pWvh, g_Wvh);
        cudaGetSymbolAddress((void**)&pW1h, g_W1h);
        cudaGetSymbolAddress((void**)&pW2h, g_W2h);
        cudaGetSymbolAddress((void**)&pHh, g_Hh);
        cudaGetSymbolAddress((void**)&pFh, g_Fh);
    }

    constexpr int WE = CH * CD * CDK;   // 1M elems per W
    k_valid<<<ROWS, 256>>>(x, pValid);
    k_cvt<<<ROWS * CD / 1024, 256>>>(x, pXh);
    k_cvt<<<WE / 1024, 256>>>(Wq, pWqh);
    k_cvt<<<WE / 1024, 256>>>(Wk, pWkh);
    k_cvt<<<WE / 1024, 256>>>(Wv, pWvh);
    k_cvt<<<CD * CD / 1024, 256>>>(fc1_w, pW1h);
    k_cvt<<<CD * CD / 1024, 256>>>(fc2_w, pW2h);

    k_qkv16<<<dim3(24, 32), 256>>>(pXh, pWqh, pWkh, pWvh, pQ, pK, pV);
    k_flash<<<dim3(8, BH), 256>>>(pQ, pK, pV, pValid, pZ);
    k_addln<true><<<ROWS, 256>>>(x, pZ, ln1_g, ln1_b, pH, pHh);
    k_fc1<<<dim3(8, 32), 256>>>(pHh, pW1h, fc1_b, pValid, pFh);
    k_fc2<<<dim3(8, 32), 256>>>(pFh, pW2h, fc2_b, pValid, pG);
    k_addln<false><<<ROWS, 256>>>(pH, pG, ln2_g, ln2_b, out, nullptr);
}

// round 13
// speedup vs baseline: 1.3499x; 1.0231x over previous
#include <cuda_runtime.h>
#include <cuda_fp16.h>
#include <math.h>
#include <stdint.h>

// Problem dims
constexpr int CB  = 4;
constexpr int CS  = 1024;
constexpr int CD  = 1024;
constexpr int CH  = 16;
constexpr int CDK = 64;
constexpr int BH   = CB * CH;   // 64
constexpr int ROWS = CB * CS;   // 4096
constexpr float LN_EPS = 1e-5f;

// Scratch (device globals: no cudaMalloc allowed)
__device__ float g_valid[ROWS];
__device__ float g_Z[(size_t)ROWS * CD];
__device__ float g_Hb[(size_t)ROWS * CD];
__device__ float g_G[(size_t)ROWS * CD];
// fp16 tensors
__device__ __half g_Qh[(size_t)BH * CS * CDK];
__device__ __half g_Kh[(size_t)BH * CS * CDK];
__device__ __half g_Vh[(size_t)BH * CS * CDK];
__device__ __half g_xh[(size_t)ROWS * CD];
__device__ __half g_Wqh[(size_t)CH * CD * CDK];
__device__ __half g_Wkh[(size_t)CH * CD * CDK];
__device__ __half g_Wvh[(size_t)CH * CD * CDK];
__device__ __half g_W1h[(size_t)CD * CD];
__device__ __half g_W2h[(size_t)CD * CD];
__device__ __half g_Hh[(size_t)ROWS * CD];
__device__ __half g_Fh[(size_t)ROWS * CD];

// ---------------- helpers ----------------
__device__ __forceinline__ float warpSum(float v) {
    #pragma unroll
    for (int o = 16; o; o >>= 1) v += __shfl_xor_sync(0xffffffffu, v, o);
    return v;
}
__device__ __forceinline__ uint32_t packh2(float lo, float hi) {
    __half2 h = __floats2half2_rn(lo, hi);
    return *reinterpret_cast<uint32_t*>(&h);
}
__device__ __forceinline__ void mma16(float c[4], const uint32_t a[4], const uint32_t b[2]) {
    asm volatile(
        "mma.sync.aligned.m16n8k16.row.col.f32.f16.f16.f32 "
        "{%0,%1,%2,%3},{%4,%5,%6,%7},{%8,%9},{%0,%1,%2,%3};"
        : "+f"(c[0]), "+f"(c[1]), "+f"(c[2]), "+f"(c[3])
        : "r"(a[0]), "r"(a[1]), "r"(a[2]), "r"(a[3]), "r"(b[0]), "r"(b[1]));
}

// ---------------- fp32 -> fp16 convert ----------------
__global__ void k_cvt(const float* __restrict__ s, __half* __restrict__ d) {
    int i = blockIdx.x * 256 + threadIdx.x;
    float4 v = ((const float4*)s)[i];
    uint2 u = { packh2(v.x, v.y), packh2(v.z, v.w) };
    ((uint2*)d)[i] = u;
}

// ---------------- fp16-input MMA GEMM core, 128x128 tile ----------------
// BK=32, 256 threads = 8 warps (4 row x 2 col); warp tile 32(M) x 64(N).
// smem rows: 16 half2 pairs along k, stride 20 words (conflict-free).
template<bool NN>
__device__ __forceinline__ void gemm16(const __half* __restrict__ A, int lda,
                                       const __half* __restrict__ B, int ldb,
                                       float acc[2][8][4]) {
    __shared__ uint32_t sA[128 * 20];
    __shared__ uint32_t sB[128 * 20];
    const int t = threadIdx.x, lane = t & 31, w = t >> 5;
    const int wr = w >> 1, wc = w & 1;
    const int rA = lane >> 2, qq = lane & 3;

    for (int k0 = 0; k0 < CD; k0 += 32) {
        #pragma unroll
        for (int i = 0; i < 2; i++) {
            int idx = t + (i << 8);
            int row = idx >> 2, c8 = (idx & 3) << 3;
            *(uint4*)&sA[row * 20 + (c8 >> 1)] =
                *(const uint4*)(A + (size_t)row * lda + k0 + c8);
        }
        if (NN) {
            #pragma unroll
            for (int i = 0; i < 2; i++) {
                int k2 = t & 15;
                int g  = (t >> 4) + (i << 4);
                int n4 = g << 2;
                const __half* bb = B + ((n4 >> 6) ? (CD * CDK) : 0)
                                     + (size_t)(k0 + 2 * k2) * CDK + (n4 & 63);
                uint2 v0 = *(const uint2*)bb;
                uint2 v1 = *(const uint2*)(bb + CDK);
                sB[(n4 + 0) * 20 + k2] = __byte_perm(v0.x, v1.x, 0x5410);
                sB[(n4 + 1) * 20 + k2] = __byte_perm(v0.x, v1.x, 0x7632);
                sB[(n4 + 2) * 20 + k2] = __byte_perm(v0.y, v1.y, 0x5410);
                sB[(n4 + 3) * 20 + k2] = __byte_perm(v0.y, v1.y, 0x7632);
            }
        } else {
            #pragma unroll
            for (int i = 0; i < 2; i++) {
                int idx = t + (i << 8);
                int n = idx >> 2, c8 = (idx & 3) << 3;
                *(uint4*)&sB[n * 20 + (c8 >> 1)] =
                    *(const uint4*)(B + (size_t)n * ldb + k0 + c8);
            }
        }
        __syncthreads();

        #pragma unroll
        for (int ks = 0; ks < 2; ks++) {
            const int pb = (ks << 3) + qq;
            uint32_t af[2][4], bf[8][2];
            #pragma unroll
            for (int ms = 0; ms < 2; ms++) {
                int r0 = wr * 32 + ms * 16 + rA;
                af[ms][0] = sA[r0 * 20 + pb];
                af[ms][1] = sA[(r0 + 8) * 20 + pb];
                af[ms][2] = sA[r0 * 20 + pb + 4];
                af[ms][3] = sA[(r0 + 8) * 20 + pb + 4];
            }
            #pragma unroll
            for (int ns = 0; ns < 8; ns++) {
                int n0 = wc * 64 + ns * 8 + rA;
                bf[ns][0] = sB[n0 * 20 + pb];
                bf[ns][1] = sB[n0 * 20 + pb + 4];
            }
            #pragma unroll
            for (int ms = 0; ms < 2; ms++)
                #pragma unroll
                for (int ns = 0; ns < 8; ns++)
                    mma16(acc[ms][ns], af[ms], bf[ns]);
        }
        __syncthreads();
    }
}

// ---------------- valid-row flags ----------------
__global__ void k_valid(const float* __restrict__ x, float* __restrict__ valid) {
    int row = blockIdx.x;
    const float* xr = x + (size_t)row * CD;
    int any = 0;
    for (int i = threadIdx.x; i < CD; i += blockDim.x) any |= (xr[i] != 0.0f);
    any = __syncthreads_or(any);
    if (threadIdx.x == 0) valid[row] = any ? 1.0f : 0.0f;
}

// ---------------- QKV projection (fp16 in, fp16 out), 2 heads per tile ---------
// grid: (24 = 3 which x 8 head-pairs, 32 row tiles). Q gets 0.125 scale folded in.
__global__ void __launch_bounds__(256)
k_qkv16(const __half* __restrict__ xh,
        const __half* __restrict__ Wqh, const __half* __restrict__ Wkh,
        const __half* __restrict__ Wvh,
        __half* __restrict__ pQ, __half* __restrict__ pK, __half* __restrict__ pV) {
    int which = blockIdx.x >> 3, hp = blockIdx.x & 7;
    int b = blockIdx.y >> 3, s0 = (blockIdx.y & 7) << 7;
    const __half* W = (which == 0 ? Wqh : which == 1 ? Wkh : Wvh)
                      + (size_t)hp * 2 * CD * CDK;
    const __half* A = xh + ((size_t)b * CS + s0) * CD;
    __half* P = (which == 0 ? pQ : which == 1 ? pK : pV);
    const float sc = (which == 0) ? 0.125f : 1.0f;

    float acc[2][8][4] = {};
    gemm16<true>(A, CD, W, CDK, acc);

    int lane = threadIdx.x & 31, w = threadIdx.x >> 5, wr = w >> 1, wc = w & 1;
    int head = hp * 2 + wc;
    __half* out = P + ((size_t)(b * 16 + head) * CS + s0) * CDK;
    #pragma unroll
    for (int ms = 0; ms < 2; ms++)
        #pragma unroll
        for (int ns = 0; ns < 8; ns++) {
            int r = wr * 32 + ms * 16 + (lane >> 2);
            int e = ns * 8 + ((lane & 3) << 1);
            *(uint32_t*)&out[(size_t)r * CDK + e] =
                packh2(acc[ms][ns][0] * sc, acc[ms][ns][1] * sc);
            *(uint32_t*)&out[(size_t)(r + 8) * CDK + e] =
                packh2(acc[ms][ns][2] * sc, acc[ms][ns][3] * sc);
        }
}

// ---------------- fused flash attention (fp16 Q/K/V, tile skip) ----------------
__global__ void __launch_bounds__(256)
k_flash(const __half* __restrict__ pQ, const __half* __restrict__ pK,
        const __half* __restrict__ pV, const float* __restrict__ valid,
        float* __restrict__ pZ) {
    __shared__ uint32_t sK[64 * 36];
    __shared__ uint32_t sV[64 * 36];
    const int bh = blockIdx.y, b = bh >> 4, h = bh & 15;
    const int q0 = blockIdx.x * 128;
    const int t = threadIdx.x, lane = t & 31, w = t >> 5;
    const int rA = lane >> 2;
    const int qq = lane & 3;
    const float* vbase = valid + b * CS;

    // Q fragments: fp16 pairs are contiguous -> direct aligned 32-bit loads
    const __half* Qb = pQ + ((size_t)bh * CS + q0 + w * 16) * CDK;
    uint32_t qf[4][4];
    #pragma unroll
    for (int s = 0; s < 4; s++) {
        int k = s * 16 + (qq << 1);
        qf[s][0] = *(const uint32_t*)(Qb + (size_t)rA * CDK + k);
        qf[s][1] = *(const uint32_t*)(Qb + (size_t)(rA + 8) * CDK + k);
        qf[s][2] = *(const uint32_t*)(Qb + (size_t)rA * CDK + k + 8);
        qf[s][3] = *(const uint32_t*)(Qb + (size_t)(rA + 8) * CDK + k + 8);
    }

    float acc_o[8][4] = {};
    float mA = -INFINITY, mB = -INFINITY, lA = 0.f, lB = 0.f;

    for (int kt = 0; kt < 16; kt++) {
        // prefix-mask early exit: first key invalid => whole remainder masked
        if (vbase[kt * 64] == 0.f) break;
        __syncthreads();
        const __half* Kg = pK + ((size_t)bh * CS + kt * 64) * CDK;
        const __half* Vg = pV + ((size_t)bh * CS + kt * 64) * CDK;
        // K: straight copy (pairs along headdim are natural)
        #pragma unroll
        for (int i = 0; i < 2; i++) {
            int idx = t + (i << 8);
            int row = idx >> 3, c8 = (idx & 7) << 3;
            *(uint4*)&sK[row * 36 + (c8 >> 1)] =
                *(const uint4*)(Kg + (size_t)row * CDK + c8);
        }
        // V: transpose to [hd][key-pair] via byte_perm
        #pragma unroll
        for (int i = 0; i < 2; i++) {
            int k2 = (t >> 4) + (i << 4);
            int n4 = (t & 15) << 2;
            const __half* vv = Vg + (size_t)(2 * k2) * CDK + n4;
            uint2 v0 = *(const uint2*)vv;
            uint2 v1 = *(const uint2*)(vv + CDK);
            sV[(n4 + 0) * 36 + k2] = __byte_perm(v0.x, v1.x, 0x5410);
            sV[(n4 + 1) * 36 + k2] = __byte_perm(v0.x, v1.x, 0x7632);
            sV[(n4 + 2) * 36 + k2] = __byte_perm(v0.y, v1.y, 0x5410);
            sV[(n4 + 3) * 36 + k2] = __byte_perm(v0.y, v1.y, 0x7632);
        }
        __syncthreads();

        float accs[8][4] = {};
        #pragma unroll
        for (int s = 0; s < 4; s++) {
            const int pb = (s << 3) + qq;
            #pragma unroll
            for (int j = 0; j < 8; j++) {
                int n0 = j * 8 + rA;
                uint32_t bf[2] = { sK[n0 * 36 + pb], sK[n0 * 36 + pb + 4] };
                mma16(accs[j], qf[s], bf);
            }
        }

        // column mask (scale already folded into Q), row max
        float rmaxA = -INFINITY, rmaxB = -INFINITY;
        #pragma unroll
        for (int j = 0; j < 8; j++) {
            int cg = kt * 64 + j * 8 + (qq << 1);
            float cm0 = vbase[cg], cm1 = vbase[cg + 1];
            accs[j][0] = (cm0 != 0.f) ? accs[j][0] : -1e30f;
            accs[j][1] = (cm1 != 0.f) ? accs[j][1] : -1e30f;
            accs[j][2] = (cm0 != 0.f) ? accs[j][2] : -1e30f;
            accs[j][3] = (cm1 != 0.f) ? accs[j][3] : -1e30f;
            rmaxA = fmaxf(rmaxA, fmaxf(accs[j][0], accs[j][1]));
            rmaxB = fmaxf(rmaxB, fmaxf(accs[j][2], accs[j][3]));
        }
        rmaxA = fmaxf(rmaxA, __shfl_xor_sync(~0u, rmaxA, 1));
        rmaxA = fmaxf(rmaxA, __shfl_xor_sync(~0u, rmaxA, 2));
        rmaxB = fmaxf(rmaxB, __shfl_xor_sync(~0u, rmaxB, 1));
        rmaxB = fmaxf(rmaxB, __shfl_xor_sync(~0u, rmaxB, 2));

        float mnA = fmaxf(mA, rmaxA), mnB = fmaxf(mB, rmaxB);
        float aAf = __expf(mA - mnA), aBf = __expf(mB - mnB);
        mA = mnA; mB = mnB;

        float sumA = 0.f, sumB = 0.f;
        uint32_t pt2[8][2];
        #pragma unroll
        for (int j = 0; j < 8; j++) {
            float p0 = __expf(accs[j][0] - mA), p1 = __expf(accs[j][1] - mA);
            float p2 = __expf(accs[j][2] - mB), p3 = __expf(accs[j][3] - mB);
            sumA += p0 + p1; sumB += p2 + p3;
            pt2[j][0] = packh2(p0, p1);
            pt2[j][1] = packh2(p2, p3);
            acc_o[j][0] *= aAf; acc_o[j][1] *= aAf;
            acc_o[j][2] *= aBf; acc_o[j][3] *= aBf;
        }
        sumA += __shfl_xor_sync(~0u, sumA, 1); sumA += __shfl_xor_sync(~0u, sumA, 2);
        sumB += __shfl_xor_sync(~0u, sumB, 1); sumB += __shfl_xor_sync(~0u, sumB, 2);
        lA = lA * aAf + sumA; lB = lB * aBf + sumB;

        #pragma unroll
        for (int kb = 0; kb < 4; kb++) {
            uint32_t af[4] = { pt2[2 * kb][0], pt2[2 * kb][1],
                               pt2[2 * kb + 1][0], pt2[2 * kb + 1][1] };
            const int pb = (kb << 3) + qq;
            #pragma unroll
            for (int j = 0; j < 8; j++) {
                int n0 = j * 8 + rA;
                uint32_t bf[2] = { sV[n0 * 36 + pb], sV[n0 * 36 + pb + 4] };
                mma16(acc_o[j], af, bf);
            }
        }
    }

    float invA = 1.f / lA, invB = 1.f / lB;
    int qrA = q0 + w * 16 + rA, qrB = qrA + 8;
    float vfA = vbase[qrA] * invA, vfB = vbase[qrB] * invB;
    #pragma unroll
    for (int j = 0; j < 8; j++) {
        int c = j * 8 + (qq << 1);
        float2 v01 = { acc_o[j][0] * vfA, acc_o[j][1] * vfA };
        float2 v23 = { acc_o[j][2] * vfB, acc_o[j][3] * vfB };
        *(float2*)&pZ[(size_t)(b * CS + qrA) * CD + h * 64 + c] = v01;
        *(float2*)&pZ[(size_t)(b * CS + qrB) * CD + h * 64 + c] = v23;
    }
}

// ---------------- residual add + LayerNorm (optional fp16 mirror) ---------------
template<bool H16>
__global__ void k_addln(const float* __restrict__ A, const float* __restrict__ Bv,
                        const float* __restrict__ g, const float* __restrict__ bb,
                        float* __restrict__ out, __half* __restrict__ outh) {
    int row = blockIdx.x, t = threadIdx.x;
    float4 a = ((const float4*)(A  + (size_t)row * CD))[t];
    float4 b = ((const float4*)(Bv + (size_t)row * CD))[t];
    float4 v = {a.x + b.x, a.y + b.y, a.z + b.z, a.w + b.w};
    float s = v.x + v.y + v.z + v.w;
    float q = v.x * v.x + v.y * v.y + v.z * v.z + v.w * v.w;
    __shared__ float sr1[8];
    __shared__ float sr2[8];
    s = warpSum(s); q = warpSum(q);
    if ((t & 31) == 0) { sr1[t >> 5] = s; sr2[t >> 5] = q; }
    __syncthreads();
    float S = 0.f, Q = 0.f;
    #pragma unroll
    for (int i = 0; i < 8; i++) { S += sr1[i]; Q += sr2[i]; }
    float mu = S * (1.0f / CD);
    float var = Q * (1.0f / CD) - mu * mu;
    float rs = rsqrtf(var + LN_EPS);
    float4 gg = ((const float4*)g)[t];
    float4 bv2 = ((const float4*)bb)[t];
    float4 o;
    o.x = (v.x - mu) * rs * gg.x + bv2.x;
    o.y = (v.y - mu) * rs * gg.y + bv2.y;
    o.z = (v.z - mu) * rs * gg.z + bv2.z;
    o.w = (v.w - mu) * rs * gg.w + bv2.w;
    ((float4*)(out + (size_t)row * CD))[t] = o;
    if (H16) {
        uint2 u = { packh2(o.x, o.y), packh2(o.z, o.w) };
        ((uint2*)(outh + (size_t)row * CD))[t] = u;
    }
}

// ---------------- FC1: fp16 in -> relu*valid -> fp16 out ----------------
__global__ void __launch_bounds__(256)
k_fc1(const __half* __restrict__ A, const __half* __restrict__ W,
      const float* __restrict__ bias, const float* __restrict__ valid,
      __half* __restrict__ outh) {
    int j0 = blockIdx.x * 128, r0 = blockIdx.y * 128;
    float acc[2][8][4] = {};
    gemm16<false>(A + (size_t)r0 * CD, CD, W + (size_t)j0 * CD, CD, acc);

    int lane = threadIdx.x & 31, w = threadIdx.x >> 5, wr = w >> 1, wc = w & 1;
    #pragma unroll
    for (int ms = 0; ms < 2; ms++)
        #pragma unroll
        for (int ns = 0; ns < 8; ns++) {
            int r = wr * 32 + ms * 16 + (lane >> 2);
            int c = wc * 64 + ns * 8 + ((lane & 3) << 1);
            float b0 = bias[j0 + c], b1 = bias[j0 + c + 1];
            float vf0 = valid[r0 + r], vf1 = valid[r0 + r + 8];
            float t0 = fmaxf(acc[ms][ns][0] + b0, 0.f) * vf0;
            float t1 = fmaxf(acc[ms][ns][1] + b1, 0.f) * vf0;
            float t2 = fmaxf(acc[ms][ns][2] + b0, 0.f) * vf1;
            float t3 = fmaxf(acc[ms][ns][3] + b1, 0.f) * vf1;
            *(uint32_t*)&outh[(size_t)(r0 + r) * CD + j0 + c]     = packh2(t0, t1);
            *(uint32_t*)&outh[(size_t)(r0 + r + 8) * CD + j0 + c] = packh2(t2, t3);
        }
}

// ---------------- FC2: fp16 in -> +bias, *valid -> fp32 out ----------------
__global__ void __launch_bounds__(256)
k_fc2(const __half* __restrict__ A, const __half* __restrict__ W,
      const float* __restrict__ bias, const float* __restrict__ valid,
      float* __restrict__ out) {
    int j0 = blockIdx.x * 128, r0 = blockIdx.y * 128;
    float acc[2][8][4] = {};
    gemm16<false>(A + (size_t)r0 * CD, CD, W + (size_t)j0 * CD, CD, acc);

    int lane = threadIdx.x & 31, w = threadIdx.x >> 5, wr = w >> 1, wc = w & 1;
    #pragma unroll
    for (int ms = 0; ms < 2; ms++)
        #pragma unroll
        for (int ns = 0; ns < 8; ns++) {
            int r = wr * 32 + ms * 16 + (lane >> 2);
            int c = wc * 64 + ns * 8 + ((lane & 3) << 1);
            float b0 = bias[j0 + c], b1 = bias[j0 + c + 1];
            float vf0 = valid[r0 + r], vf1 = valid[r0 + r + 8];
            float2 v01 = { (acc[ms][ns][0] + b0) * vf0, (acc[ms][ns][1] + b1) * vf0 };
            float2 v23 = { (acc[ms][ns][2] + b0) * vf1, (acc[ms][ns][3] + b1) * vf1 };
            *(float2*)&out[(size_t)(r0 + r) * CD + j0 + c] = v01;
            *(float2*)&out[(size_t)(r0 + r + 8) * CD + j0 + c] = v23;
        }
}

// ---------------- launch ----------------
extern "C" void kernel_launch(void* const* d_in, const int* in_sizes, int n_in,
                              void* d_out, int out_size) {
    const float* x     = (const float*)d_in[0];
    const float* Wq    = (const float*)d_in[1];
    const float* Wk    = (const float*)d_in[2];
    const float* Wv    = (const float*)d_in[3];
    const float* ln1_g = (const float*)d_in[4];
    const float* ln1_b = (const float*)d_in[5];
    const float* fc1_w = (const float*)d_in[6];
    const float* fc1_b = (const float*)d_in[7];
    const float* fc2_w = (const float*)d_in[8];
    const float* fc2_b = (const float*)d_in[9];
    const float* ln2_g = (const float*)d_in[10];
    const float* ln2_b = (const float*)d_in[11];
    float* out = (float*)d_out;

    static float *pValid = nullptr, *pZ, *pH, *pG;
    static __half *pQh, *pKh, *pVh, *pXh, *pWqh, *pWkh, *pWvh, *pW1h, *pW2h, *pHh, *pFh;
    if (!pValid) {
        cudaGetSymbolAddress((void**)&pValid, g_valid);
        cudaGetSymbolAddress((void**)&pZ, g_Z);
        cudaGetSymbolAddress((void**)&pH, g_Hb);
        cudaGetSymbolAddress((void**)&pG, g_G);
        cudaGetSymbolAddress((void**)&pQh, g_Qh);
        cudaGetSymbolAddress((void**)&pKh, g_Kh);
        cudaGetSymbolAddress((void**)&pVh, g_Vh);
        cudaGetSymbolAddress((void**)&pXh, g_xh);
        cudaGetSymbolAddress((void**)&pWqh, g_Wqh);
        cudaGetSymbolAddress((void**)&pWkh, g_Wkh);
        cudaGetSymbolAddress((void**)&pWvh, g_Wvh);
        cudaGetSymbolAddress((void**)&pW1h, g_W1h);
        cudaGetSymbolAddress((void**)&pW2h, g_W2h);
        cudaGetSymbolAddress((void**)&pHh, g_Hh);
        cudaGetSymbolAddress((void**)&pFh, g_Fh);
    }

    constexpr int WE = CH * CD * CDK;
    k_valid<<<ROWS, 256>>>(x, pValid);
    k_cvt<<<ROWS * CD / 1024, 256>>>(x, pXh);
    k_cvt<<<WE / 1024, 256>>>(Wq, pWqh);
    k_cvt<<<WE / 1024, 256>>>(Wk, pWkh);
    k_cvt<<<WE / 1024, 256>>>(Wv, pWvh);
    k_cvt<<<CD * CD / 1024, 256>>>(fc1_w, pW1h);
    k_cvt<<<CD * CD / 1024, 256>>>(fc2_w, pW2h);

    k_qkv16<<<dim3(24, 32), 256>>>(pXh, pWqh, pWkh, pWvh, pQh, pKh, pVh);
    k_flash<<<dim3(8, BH), 256>>>(pQh, pKh, pVh, pValid, pZ);
    k_addln<true><<<ROWS, 256>>>(x, pZ, ln1_g, ln1_b, pH, pHh);
    k_fc1<<<dim3(8, 32), 256>>>(pHh, pW1h, fc1_b, pValid, pFh);
    k_fc2<<<dim3(8, 32), 256>>>(pFh, pW2h, fc2_b, pValid, pG);
    k_addln<false><<<ROWS, 256>>>(pH, pG, ln2_g, ln2_b, out, nullptr);
}

// round 14
// speedup vs baseline: 1.5228x; 1.1281x over previous
#include <cuda_runtime.h>
#include <cuda_fp16.h>
#include <math.h>
#include <stdint.h>

// Problem dims
constexpr int CB  = 4;
constexpr int CS  = 1024;
constexpr int CD  = 1024;
constexpr int CH  = 16;
constexpr int CDK = 64;
constexpr int BH   = CB * CH;   // 64
constexpr int ROWS = CB * CS;   // 4096
constexpr float LN_EPS = 1e-5f;

// Scratch (device globals: no cudaMalloc allowed)
__device__ float g_valid[ROWS];
__device__ float g_Z[(size_t)ROWS * CD];
__device__ float g_Hb[(size_t)ROWS * CD];
__device__ float g_G[(size_t)ROWS * CD];
// fp16 tensors
__device__ __half g_Qh[(size_t)BH * CS * CDK];
__device__ __half g_Kh[(size_t)BH * CS * CDK];
__device__ __half g_Vh[(size_t)BH * CS * CDK];
__device__ __half g_xh[(size_t)ROWS * CD];
__device__ __half g_Wqh[(size_t)CH * CD * CDK];
__device__ __half g_Wkh[(size_t)CH * CD * CDK];
__device__ __half g_Wvh[(size_t)CH * CD * CDK];
__device__ __half g_W1h[(size_t)CD * CD];
__device__ __half g_W2h[(size_t)CD * CD];
__device__ __half g_Hh[(size_t)ROWS * CD];
__device__ __half g_Fh[(size_t)ROWS * CD];

// ---------------- helpers ----------------
__device__ __forceinline__ float warpSum(float v) {
    #pragma unroll
    for (int o = 16; o; o >>= 1) v += __shfl_xor_sync(0xffffffffu, v, o);
    return v;
}
__device__ __forceinline__ uint32_t packh2(float lo, float hi) {
    __half2 h = __floats2half2_rn(lo, hi);
    return *reinterpret_cast<uint32_t*>(&h);
}
__device__ __forceinline__ void mma16(float c[4], const uint32_t a[4], const uint32_t b[2]) {
    asm volatile(
        "mma.sync.aligned.m16n8k16.row.col.f32.f16.f16.f32 "
        "{%0,%1,%2,%3},{%4,%5,%6,%7},{%8,%9},{%0,%1,%2,%3};"
        : "+f"(c[0]), "+f"(c[1]), "+f"(c[2]), "+f"(c[3])
        : "r"(a[0]), "r"(a[1]), "r"(a[2]), "r"(a[3]), "r"(b[0]), "r"(b[1]));
}
__device__ __forceinline__ void ldsm4(uint32_t& r0, uint32_t& r1, uint32_t& r2, uint32_t& r3,
                                      uint32_t saddr) {
    asm volatile("ldmatrix.sync.aligned.m8n8.x4.shared.b16 {%0,%1,%2,%3}, [%4];"
        : "=r"(r0), "=r"(r1), "=r"(r2), "=r"(r3) : "r"(saddr));
}

// ---------------- merged fp32 -> fp16 convert (6 tensors, one launch) ----------
// grid: 4096 (x) + 5*1024 (Wq,Wk,Wv,fc1_w,fc2_w) = 9216 blocks, 1024 elems/block
__global__ void k_cvt6(const float* __restrict__ x,
                       const float* __restrict__ wq, const float* __restrict__ wk,
                       const float* __restrict__ wv, const float* __restrict__ w1,
                       const float* __restrict__ w2,
                       __half* xh, __half* wqh, __half* wkh, __half* wvh,
                       __half* w1h, __half* w2h) {
    int bid = blockIdx.x;
    const float* s; __half* d; int off;
    if (bid < 4096) { s = x; d = xh; off = bid; }
    else {
        int t2 = bid - 4096;
        int which = t2 >> 10; off = t2 & 1023;
        if      (which == 0) { s = wq; d = wqh; }
        else if (which == 1) { s = wk; d = wkh; }
        else if (which == 2) { s = wv; d = wvh; }
        else if (which == 3) { s = w1; d = w1h; }
        else                 { s = w2; d = w2h; }
    }
    int i = off * 256 + threadIdx.x;
    float4 v = ((const float4*)s)[i];
    uint2 u = { packh2(v.x, v.y), packh2(v.z, v.w) };
    ((uint2*)d)[i] = u;
}

// ---------------- fp16 MMA GEMM core, 128x128 tile, ldmatrix frags --------------
// BK=32, 256 threads = 8 warps (4 row x 2 col); warp tile 32(M) x 64(N).
// smem rows: 16 half2 pairs along k, stride 20 words (LDSM conflict-free).
template<bool NN>
__device__ __forceinline__ void gemm16(const __half* __restrict__ A, int lda,
                                       const __half* __restrict__ B, int ldb,
                                       float acc[2][8][4]) {
    __shared__ __align__(16) uint32_t sA[128 * 20];
    __shared__ __align__(16) uint32_t sB[128 * 20];
    const int t = threadIdx.x, lane = t & 31, w = t >> 5;
    const int wr = w >> 1, wc = w & 1;
    const uint32_t sAb = (uint32_t)__cvta_generic_to_shared(sA);
    const uint32_t sBb = (uint32_t)__cvta_generic_to_shared(sB);

    for (int k0 = 0; k0 < CD; k0 += 32) {
        #pragma unroll
        for (int i = 0; i < 2; i++) {
            int idx = t + (i << 8);
            int row = idx >> 2, c8 = (idx & 3) << 3;
            *(uint4*)&sA[row * 20 + (c8 >> 1)] =
                *(const uint4*)(A + (size_t)row * lda + k0 + c8);
        }
        if (NN) {
            #pragma unroll
            for (int i = 0; i < 2; i++) {
                int k2 = t & 15;
                int g  = (t >> 4) + (i << 4);
                int n4 = g << 2;
                const __half* bb = B + ((n4 >> 6) ? (CD * CDK) : 0)
                                     + (size_t)(k0 + 2 * k2) * CDK + (n4 & 63);
                uint2 v0 = *(const uint2*)bb;
                uint2 v1 = *(const uint2*)(bb + CDK);
                sB[(n4 + 0) * 20 + k2] = __byte_perm(v0.x, v1.x, 0x5410);
                sB[(n4 + 1) * 20 + k2] = __byte_perm(v0.x, v1.x, 0x7632);
                sB[(n4 + 2) * 20 + k2] = __byte_perm(v0.y, v1.y, 0x5410);
                sB[(n4 + 3) * 20 + k2] = __byte_perm(v0.y, v1.y, 0x7632);
            }
        } else {
            #pragma unroll
            for (int i = 0; i < 2; i++) {
                int idx = t + (i << 8);
                int n = idx >> 2, c8 = (idx & 3) << 3;
                *(uint4*)&sB[n * 20 + (c8 >> 1)] =
                    *(const uint4*)(B + (size_t)n * ldb + k0 + c8);
            }
        }
        __syncthreads();

        #pragma unroll
        for (int ks = 0; ks < 2; ks++) {
            uint32_t af[2][4], bf[8][2];
            #pragma unroll
            for (int ms = 0; ms < 2; ms++) {
                int row  = wr * 32 + ms * 16 + (lane & 15);
                int word = ks * 8 + ((lane >> 4) << 2);
                ldsm4(af[ms][0], af[ms][1], af[ms][2], af[ms][3],
                      sAb + (row * 20 + word) * 4);
            }
            #pragma unroll
            for (int p = 0; p < 4; p++) {
                int row  = wc * 64 + p * 16 + ((lane >> 4) << 3) + (lane & 7);
                int word = ks * 8 + (((lane >> 3) & 1) << 2);
                ldsm4(bf[2 * p][0], bf[2 * p][1], bf[2 * p + 1][0], bf[2 * p + 1][1],
                      sBb + (row * 20 + word) * 4);
            }
            #pragma unroll
            for (int ms = 0; ms < 2; ms++)
                #pragma unroll
                for (int ns = 0; ns < 8; ns++)
                    mma16(acc[ms][ns], af[ms], bf[ns]);
        }
        __syncthreads();
    }
}

// ---------------- valid-row flags ----------------
__global__ void k_valid(const float* __restrict__ x, float* __restrict__ valid) {
    int row = blockIdx.x;
    const float* xr = x + (size_t)row * CD;
    int any = 0;
    for (int i = threadIdx.x; i < CD; i += blockDim.x) any |= (xr[i] != 0.0f);
    any = __syncthreads_or(any);
    if (threadIdx.x == 0) valid[row] = any ? 1.0f : 0.0f;
}

// ---------------- QKV projection (fp16 in/out), 2 heads per tile ----------------
__global__ void __launch_bounds__(256)
k_qkv16(const __half* __restrict__ xh,
        const __half* __restrict__ Wqh, const __half* __restrict__ Wkh,
        const __half* __restrict__ Wvh,
        __half* __restrict__ pQ, __half* __restrict__ pK, __half* __restrict__ pV) {
    int which = blockIdx.x >> 3, hp = blockIdx.x & 7;
    int b = blockIdx.y >> 3, s0 = (blockIdx.y & 7) << 7;
    const __half* W = (which == 0 ? Wqh : which == 1 ? Wkh : Wvh)
                      + (size_t)hp * 2 * CD * CDK;
    const __half* A = xh + ((size_t)b * CS + s0) * CD;
    __half* P = (which == 0 ? pQ : which == 1 ? pK : pV);
    const float sc = (which == 0) ? 0.125f : 1.0f;

    float acc[2][8][4] = {};
    gemm16<true>(A, CD, W, CDK, acc);

    int lane = threadIdx.x & 31, w = threadIdx.x >> 5, wr = w >> 1, wc = w & 1;
    int head = hp * 2 + wc;
    __half* out = P + ((size_t)(b * 16 + head) * CS + s0) * CDK;
    #pragma unroll
    for (int ms = 0; ms < 2; ms++)
        #pragma unroll
        for (int ns = 0; ns < 8; ns++) {
            int r = wr * 32 + ms * 16 + (lane >> 2);
            int e = ns * 8 + ((lane & 3) << 1);
            *(uint32_t*)&out[(size_t)r * CDK + e] =
                packh2(acc[ms][ns][0] * sc, acc[ms][ns][1] * sc);
            *(uint32_t*)&out[(size_t)(r + 8) * CDK + e] =
                packh2(acc[ms][ns][2] * sc, acc[ms][ns][3] * sc);
        }
}

// ---------------- fused flash attention (fp16, ldmatrix, tile skip) -------------
__global__ void __launch_bounds__(256)
k_flash(const __half* __restrict__ pQ, const __half* __restrict__ pK,
        const __half* __restrict__ pV, const float* __restrict__ valid,
        float* __restrict__ pZ) {
    __shared__ __align__(16) uint32_t sK[64 * 36];
    __shared__ __align__(16) uint32_t sV[64 * 36];
    const int bh = blockIdx.y, b = bh >> 4, h = bh & 15;
    const int q0 = blockIdx.x * 128;
    const int t = threadIdx.x, lane = t & 31, w = t >> 5;
    const int rA = lane >> 2;
    const int qq = lane & 3;
    const float* vbase = valid + b * CS;
    const uint32_t sKb = (uint32_t)__cvta_generic_to_shared(sK);
    const uint32_t sVb = (uint32_t)__cvta_generic_to_shared(sV);
    // ldmatrix B-address components (shared by S and PV phases)
    const int lrow  = ((lane >> 4) << 3) + (lane & 7);
    const int lword = (((lane >> 3) & 1) << 2);

    const __half* Qb = pQ + ((size_t)bh * CS + q0 + w * 16) * CDK;
    uint32_t qf[4][4];
    #pragma unroll
    for (int s = 0; s < 4; s++) {
        int k = s * 16 + (qq << 1);
        qf[s][0] = *(const uint32_t*)(Qb + (size_t)rA * CDK + k);
        qf[s][1] = *(const uint32_t*)(Qb + (size_t)(rA + 8) * CDK + k);
        qf[s][2] = *(const uint32_t*)(Qb + (size_t)rA * CDK + k + 8);
        qf[s][3] = *(const uint32_t*)(Qb + (size_t)(rA + 8) * CDK + k + 8);
    }

    float acc_o[8][4] = {};
    float mA = -INFINITY, mB = -INFINITY, lA = 0.f, lB = 0.f;

    for (int kt = 0; kt < 16; kt++) {
        if (vbase[kt * 64] == 0.f) break;   // prefix mask: remainder fully masked
        __syncthreads();
        const __half* Kg = pK + ((size_t)bh * CS + kt * 64) * CDK;
        const __half* Vg = pV + ((size_t)bh * CS + kt * 64) * CDK;
        #pragma unroll
        for (int i = 0; i < 2; i++) {
            int idx = t + (i << 8);
            int row = idx >> 3, c8 = (idx & 7) << 3;
            *(uint4*)&sK[row * 36 + (c8 >> 1)] =
                *(const uint4*)(Kg + (size_t)row * CDK + c8);
        }
        #pragma unroll
        for (int i = 0; i < 2; i++) {
            int k2 = (t >> 4) + (i << 4);
            int n4 = (t & 15) << 2;
            const __half* vv = Vg + (size_t)(2 * k2) * CDK + n4;
            uint2 v0 = *(const uint2*)vv;
            uint2 v1 = *(const uint2*)(vv + CDK);
            sV[(n4 + 0) * 36 + k2] = __byte_perm(v0.x, v1.x, 0x5410);
            sV[(n4 + 1) * 36 + k2] = __byte_perm(v0.x, v1.x, 0x7632);
            sV[(n4 + 2) * 36 + k2] = __byte_perm(v0.y, v1.y, 0x5410);
            sV[(n4 + 3) * 36 + k2] = __byte_perm(v0.y, v1.y, 0x7632);
        }
        __syncthreads();

        float accs[8][4] = {};
        #pragma unroll
        for (int s = 0; s < 4; s++) {
            #pragma unroll
            for (int p = 0; p < 4; p++) {
                uint32_t bf[4];
                int row = p * 16 + lrow;
                int word = (s << 3) + lword;
                ldsm4(bf[0], bf[1], bf[2], bf[3], sKb + (row * 36 + word) * 4);
                mma16(accs[2 * p],     qf[s], bf);
                mma16(accs[2 * p + 1], qf[s], bf + 2);
            }
        }

        float rmaxA = -INFINITY, rmaxB = -INFINITY;
        #pragma unroll
        for (int j = 0; j < 8; j++) {
            int cg = kt * 64 + j * 8 + (qq << 1);
            float cm0 = vbase[cg], cm1 = vbase[cg + 1];
            accs[j][0] = (cm0 != 0.f) ? accs[j][0] : -1e30f;
            accs[j][1] = (cm1 != 0.f) ? accs[j][1] : -1e30f;
            accs[j][2] = (cm0 != 0.f) ? accs[j][2] : -1e30f;
            accs[j][3] = (cm1 != 0.f) ? accs[j][3] : -1e30f;
            rmaxA = fmaxf(rmaxA, fmaxf(accs[j][0], accs[j][1]));
            rmaxB = fmaxf(rmaxB, fmaxf(accs[j][2], accs[j][3]));
        }
        rmaxA = fmaxf(rmaxA, __shfl_xor_sync(~0u, rmaxA, 1));
        rmaxA = fmaxf(rmaxA, __shfl_xor_sync(~0u, rmaxA, 2));
        rmaxB = fmaxf(rmaxB, __shfl_xor_sync(~0u, rmaxB, 1));
        rmaxB = fmaxf(rmaxB, __shfl_xor_sync(~0u, rmaxB, 2));

        float mnA = fmaxf(mA, rmaxA), mnB = fmaxf(mB, rmaxB);
        float aAf = __expf(mA - mnA), aBf = __expf(mB - mnB);
        mA = mnA; mB = mnB;

        float sumA = 0.f, sumB = 0.f;
        uint32_t pt2[8][2];
        #pragma unroll
        for (int j = 0; j < 8; j++) {
            float p0 = __expf(accs[j][0] - mA), p1 = __expf(accs[j][1] - mA);
            float p2 = __expf(accs[j][2] - mB), p3 = __expf(accs[j][3] - mB);
            sumA += p0 + p1; sumB += p2 + p3;
            pt2[j][0] = packh2(p0, p1);
            pt2[j][1] = packh2(p2, p3);
            acc_o[j][0] *= aAf; acc_o[j][1] *= aAf;
            acc_o[j][2] *= aBf; acc_o[j][3] *= aBf;
        }
        sumA += __shfl_xor_sync(~0u, sumA, 1); sumA += __shfl_xor_sync(~0u, sumA, 2);
        sumB += __shfl_xor_sync(~0u, sumB, 1); sumB += __shfl_xor_sync(~0u, sumB, 2);
        lA = lA * aAf + sumA; lB = lB * aBf + sumB;

        #pragma unroll
        for (int kb = 0; kb < 4; kb++) {
            uint32_t af[4] = { pt2[2 * kb][0], pt2[2 * kb][1],
                               pt2[2 * kb + 1][0], pt2[2 * kb + 1][1] };
            #pragma unroll
            for (int p = 0; p < 4; p++) {
                uint32_t bf[4];
                int row = p * 16 + lrow;
                int word = (kb << 3) + lword;
                ldsm4(bf[0], bf[1], bf[2], bf[3], sVb + (row * 36 + word) * 4);
                mma16(acc_o[2 * p],     af, bf);
                mma16(acc_o[2 * p + 1], af, bf + 2);
            }
        }
    }

    float invA = 1.f / lA, invB = 1.f / lB;
    int qrA = q0 + w * 16 + rA, qrB = qrA + 8;
    float vfA = vbase[qrA] * invA, vfB = vbase[qrB] * invB;
    #pragma unroll
    for (int j = 0; j < 8; j++) {
        int c = j * 8 + (qq << 1);
        float2 v01 = { acc_o[j][0] * vfA, acc_o[j][1] * vfA };
        float2 v23 = { acc_o[j][2] * vfB, acc_o[j][3] * vfB };
        *(float2*)&pZ[(size_t)(b * CS + qrA) * CD + h * 64 + c] = v01;
        *(float2*)&pZ[(size_t)(b * CS + qrB) * CD + h * 64 + c] = v23;
    }
}

// ---------------- residual add + LayerNorm (optional fp16 mirror) ---------------
template<bool H16>
__global__ void k_addln(const float* __restrict__ A, const float* __restrict__ Bv,
                        const float* __restrict__ g, const float* __restrict__ bb,
                        float* __restrict__ out, __half* __restrict__ outh) {
    int row = blockIdx.x, t = threadIdx.x;
    float4 a = ((const float4*)(A  + (size_t)row * CD))[t];
    float4 b = ((const float4*)(Bv + (size_t)row * CD))[t];
    float4 v = {a.x + b.x, a.y + b.y, a.z + b.z, a.w + b.w};
    float s = v.x + v.y + v.z + v.w;
    float q = v.x * v.x + v.y * v.y + v.z * v.z + v.w * v.w;
    __shared__ float sr1[8];
    __shared__ float sr2[8];
    s = warpSum(s); q = warpSum(q);
    if ((t & 31) == 0) { sr1[t >> 5] = s; sr2[t >> 5] = q; }
    __syncthreads();
    float S = 0.f, Q = 0.f;
    #pragma unroll
    for (int i = 0; i < 8; i++) { S += sr1[i]; Q += sr2[i]; }
    float mu = S * (1.0f / CD);
    float var = Q * (1.0f / CD) - mu * mu;
    float rs = rsqrtf(var + LN_EPS);
    float4 gg = ((const float4*)g)[t];
    float4 bv2 = ((const float4*)bb)[t];
    float4 o;
    o.x = (v.x - mu) * rs * gg.x + bv2.x;
    o.y = (v.y - mu) * rs * gg.y + bv2.y;
    o.z = (v.z - mu) * rs * gg.z + bv2.z;
    o.w = (v.w - mu) * rs * gg.w + bv2.w;
    ((float4*)(out + (size_t)row * CD))[t] = o;
    if (H16) {
        uint2 u = { packh2(o.x, o.y), packh2(o.z, o.w) };
        ((uint2*)(outh + (size_t)row * CD))[t] = u;
    }
}

// ---------------- FC1: fp16 in -> relu*valid -> fp16 out ----------------
__global__ void __launch_bounds__(256)
k_fc1(const __half* __restrict__ A, const __half* __restrict__ W,
      const float* __restrict__ bias, const float* __restrict__ valid,
      __half* __restrict__ outh) {
    int j0 = blockIdx.x * 128, r0 = blockIdx.y * 128;
    float acc[2][8][4] = {};
    gemm16<false>(A + (size_t)r0 * CD, CD, W + (size_t)j0 * CD, CD, acc);

    int lane = threadIdx.x & 31, w = threadIdx.x >> 5, wr = w >> 1, wc = w & 1;
    #pragma unroll
    for (int ms = 0; ms < 2; ms++)
        #pragma unroll
        for (int ns = 0; ns < 8; ns++) {
            int r = wr * 32 + ms * 16 + (lane >> 2);
            int c = wc * 64 + ns * 8 + ((lane & 3) << 1);
            float b0 = bias[j0 + c], b1 = bias[j0 + c + 1];
            float vf0 = valid[r0 + r], vf1 = valid[r0 + r + 8];
            float t0 = fmaxf(acc[ms][ns][0] + b0, 0.f) * vf0;
            float t1 = fmaxf(acc[ms][ns][1] + b1, 0.f) * vf0;
            float t2 = fmaxf(acc[ms][ns][2] + b0, 0.f) * vf1;
            float t3 = fmaxf(acc[ms][ns][3] + b1, 0.f) * vf1;
            *(uint32_t*)&outh[(size_t)(r0 + r) * CD + j0 + c]     = packh2(t0, t1);
            *(uint32_t*)&outh[(size_t)(r0 + r + 8) * CD + j0 + c] = packh2(t2, t3);
        }
}

// ---------------- FC2: fp16 in -> +bias, *valid -> fp32 out ----------------
__global__ void __launch_bounds__(256)
k_fc2(const __half* __restrict__ A, const __half* __restrict__ W,
      const float* __restrict__ bias, const float* __restrict__ valid,
      float* __restrict__ out) {
    int j0 = blockIdx.x * 128, r0 = blockIdx.y * 128;
    float acc[2][8][4] = {};
    gemm16<false>(A + (size_t)r0 * CD, CD, W + (size_t)j0 * CD, CD, acc);

    int lane = threadIdx.x & 31, w = threadIdx.x >> 5, wr = w >> 1, wc = w & 1;
    #pragma unroll
    for (int ms = 0; ms < 2; ms++)
        #pragma unroll
        for (int ns = 0; ns < 8; ns++) {
            int r = wr * 32 + ms * 16 + (lane >> 2);
            int c = wc * 64 + ns * 8 + ((lane & 3) << 1);
            float b0 = bias[j0 + c], b1 = bias[j0 + c + 1];
            float vf0 = valid[r0 + r], vf1 = valid[r0 + r + 8];
            float2 v01 = { (acc[ms][ns][0] + b0) * vf0, (acc[ms][ns][1] + b1) * vf0 };
            float2 v23 = { (acc[ms][ns][2] + b0) * vf1, (acc[ms][ns][3] + b1) * vf1 };
            *(float2*)&out[(size_t)(r0 + r) * CD + j0 + c] = v01;
            *(float2*)&out[(size_t)(r0 + r + 8) * CD + j0 + c] = v23;
        }
}

// ---------------- launch ----------------
extern "C" void kernel_launch(void* const* d_in, const int* in_sizes, int n_in,
                              void* d_out, int out_size) {
    const float* x     = (const float*)d_in[0];
    const float* Wq    = (const float*)d_in[1];
    const float* Wk    = (const float*)d_in[2];
    const float* Wv    = (const float*)d_in[3];
    const float* ln1_g = (const float*)d_in[4];
    const float* ln1_b = (const float*)d_in[5];
    const float* fc1_w = (const float*)d_in[6];
    const float* fc1_b = (const float*)d_in[7];
    const float* fc2_w = (const float*)d_in[8];
    const float* fc2_b = (const float*)d_in[9];
    const float* ln2_g = (const float*)d_in[10];
    const float* ln2_b = (const float*)d_in[11];
    float* out = (float*)d_out;

    static float *pValid = nullptr, *pZ, *pH, *pG;
    static __half *pQh, *pKh, *pVh, *pXh, *pWqh, *pWkh, *pWvh, *pW1h, *pW2h, *pHh, *pFh;
    if (!pValid) {
        cudaGetSymbolAddress((void**)&pValid, g_valid);
        cudaGetSymbolAddress((void**)&pZ, g_Z);
        cudaGetSymbolAddress((void**)&pH, g_Hb);
        cudaGetSymbolAddress((void**)&pG, g_G);
        cudaGetSymbolAddress((void**)&pQh, g_Qh);
        cudaGetSymbolAddress((void**)&pKh, g_Kh);
        cudaGetSymbolAddress((void**)&pVh, g_Vh);
        cudaGetSymbolAddress((void**)&pXh, g_xh);
        cudaGetSymbolAddress((void**)&pWqh, g_Wqh);
        cudaGetSymbolAddress((void**)&pWkh, g_Wkh);
        cudaGetSymbolAddress((void**)&pWvh, g_Wvh);
        cudaGetSymbolAddress((void**)&pW1h, g_W1h);
        cudaGetSymbolAddress((void**)&pW2h, g_W2h);
        cudaGetSymbolAddress((void**)&pHh, g_Hh);
        cudaGetSymbolAddress((void**)&pFh, g_Fh);
    }

    k_valid<<<ROWS, 256>>>(x, pValid);
    k_cvt6<<<9216, 256>>>(x, Wq, Wk, Wv, fc1_w, fc2_w,
                          pXh, pWqh, pWkh, pWvh, pW1h, pW2h);
    k_qkv16<<<dim3(24, 32), 256>>>(pXh, pWqh, pWkh, pWvh, pQh, pKh, pVh);
    k_flash<<<dim3(8, BH), 256>>>(pQh, pKh, pVh, pValid, pZ);
    k_addln<true><<<ROWS, 256>>>(x, pZ, ln1_g, ln1_b, pH, pHh);
    k_fc1<<<dim3(8, 32), 256>>>(pHh, pW1h, fc1_b, pValid, pFh);
    k_fc2<<<dim3(8, 32), 256>>>(pFh, pW2h, fc2_b, pValid, pG);
    k_addln<false><<<ROWS, 256>>>(pH, pG, ln2_g, ln2_b, out, nullptr);
}

// round 16
// speedup vs baseline: 2.0097x; 1.3197x over previous
#include <cuda_runtime.h>
#include <cuda_fp16.h>
#include <math.h>
#include <stdint.h>

// Problem dims
constexpr int CB  = 4;
constexpr int CS  = 1024;
constexpr int CD  = 1024;
constexpr int CH  = 16;
constexpr int CDK = 64;
constexpr int BH   = CB * CH;   // 64
constexpr int ROWS = CB * CS;   // 4096
constexpr float LN_EPS = 1e-5f;

// Scratch (device globals: no cudaMalloc allowed)
__device__ float g_valid[ROWS];
__device__ float g_Z[(size_t)ROWS * CD];
__device__ float g_Hb[(size_t)ROWS * CD];
__device__ float g_G[(size_t)ROWS * CD];
// fp16 tensors
__device__ __half g_Qh[(size_t)BH * CS * CDK];
__device__ __half g_Kh[(size_t)BH * CS * CDK];
__device__ __half g_Vh[(size_t)BH * CS * CDK];
__device__ __half g_xh[(size_t)ROWS * CD];
__device__ __half g_WqT[(size_t)CH * CDK * CD];   // transposed: [h][e][d]
__device__ __half g_WkT[(size_t)CH * CDK * CD];
__device__ __half g_WvT[(size_t)CH * CDK * CD];
__device__ __half g_W1h[(size_t)CD * CD];
__device__ __half g_W2h[(size_t)CD * CD];
__device__ __half g_Hh[(size_t)ROWS * CD];
__device__ __half g_Fh[(size_t)ROWS * CD];

// ---------------- helpers ----------------
__device__ __forceinline__ float warpSum(float v) {
    #pragma unroll
    for (int o = 16; o; o >>= 1) v += __shfl_xor_sync(0xffffffffu, v, o);
    return v;
}
__device__ __forceinline__ uint32_t packh2(float lo, float hi) {
    __half2 h = __floats2half2_rn(lo, hi);
    return *reinterpret_cast<uint32_t*>(&h);
}
__device__ __forceinline__ void mma16(float c[4], const uint32_t a[4], const uint32_t b[2]) {
    asm volatile(
        "mma.sync.aligned.m16n8k16.row.col.f32.f16.f16.f32 "
        "{%0,%1,%2,%3},{%4,%5,%6,%7},{%8,%9},{%0,%1,%2,%3};"
        : "+f"(c[0]), "+f"(c[1]), "+f"(c[2]), "+f"(c[3])
        : "r"(a[0]), "r"(a[1]), "r"(a[2]), "r"(a[3]), "r"(b[0]), "r"(b[1]));
}
__device__ __forceinline__ void ldsm4(uint32_t& r0, uint32_t& r1, uint32_t& r2, uint32_t& r3,
                                      uint32_t saddr) {
    asm volatile("ldmatrix.sync.aligned.m8n8.x4.shared.b16 {%0,%1,%2,%3}, [%4];"
        : "=r"(r0), "=r"(r1), "=r"(r2), "=r"(r3) : "r"(saddr));
}
__device__ __forceinline__ void cp16(uint32_t sdst, const void* gsrc) {
    asm volatile("cp.async.cg.shared.global [%0], [%1], 16;" :: "r"(sdst), "l"(gsrc));
}
__device__ __forceinline__ void cp_commit() { asm volatile("cp.async.commit_group;"); }
__device__ __forceinline__ void cp_wait1()  { asm volatile("cp.async.wait_group 1;"); }
__device__ __forceinline__ void cp_wait0()  { asm volatile("cp.async.wait_group 0;"); }

// ---------------- fp32 -> fp16 convert: x, fc1_w, fc2_w ----------------
__global__ void k_cvt3(const float* __restrict__ x, const float* __restrict__ w1,
                       const float* __restrict__ w2,
                       __half* xh, __half* w1h, __half* w2h) {
    int bid = blockIdx.x;
    const float* s; __half* d; int off;
    if (bid < 4096)      { s = x;  d = xh;  off = bid; }
    else if (bid < 5120) { s = w1; d = w1h; off = bid - 4096; }
    else                 { s = w2; d = w2h; off = bid - 5120; }
    int i = off * 256 + threadIdx.x;
    float4 v = ((const float4*)s)[i];
    uint2 u = { packh2(v.x, v.y), packh2(v.z, v.w) };
    ((uint2*)d)[i] = u;
}

// ---------------- QKV weight transpose+convert: [h][d][e] -> [h][e][d] ----------
// grid (16 d-tiles, 16 heads, 3 matrices), 256 threads, 64x64 tile
__global__ void k_cvtT(const float* __restrict__ wq, const float* __restrict__ wk,
                       const float* __restrict__ wv,
                       __half* wqt, __half* wkt, __half* wvt) {
    int which = blockIdx.z;
    const float* s = which == 0 ? wq : which == 1 ? wk : wv;
    __half* d = which == 0 ? wqt : which == 1 ? wkt : wvt;
    int h = blockIdx.y, d0 = blockIdx.x * 64;
    __shared__ __half sh[64][72];
    const float* base = s + ((size_t)h * CD + d0) * CDK;
    int t = threadIdx.x;
    #pragma unroll
    for (int p = 0; p < 4; p++) {
        int dr = (t >> 4) + p * 16;
        int e4 = (t & 15) << 2;
        float4 v = *(const float4*)(base + (size_t)dr * CDK + e4);
        sh[dr][e4]     = __float2half_rn(v.x);
        sh[dr][e4 + 1] = __float2half_rn(v.y);
        sh[dr][e4 + 2] = __float2half_rn(v.z);
        sh[dr][e4 + 3] = __float2half_rn(v.w);
    }
    __syncthreads();
    __half* ob = d + (size_t)h * CDK * CD + d0;
    #pragma unroll
    for (int p = 0; p < 2; p++) {
        int idx = t + (p << 8);
        int e = idx >> 3, dq = (idx & 7) << 3;
        __half tmp[8];
        #pragma unroll
        for (int j = 0; j < 8; j++) tmp[j] = sh[dq + j][e];
        *(uint4*)(ob + (size_t)e * CD + dq) = *(uint4*)tmp;
    }
}

// ---------------- fp16 MMA GEMM core: 128x128, cp.async double-buffered ---------
// BK=32, 256 threads = 8 warps (4 row x 2 col); warp tile 32(M) x 64(N).
// A[m][k] lda, B[n][k] ldb, both row-major fp16. smem stride 20 words.
__device__ __forceinline__ void gemm16(const __half* __restrict__ A, int lda,
                                       const __half* __restrict__ B, int ldb,
                                       float acc[2][8][4]) {
    __shared__ __align__(16) uint32_t sA[2][128 * 20];
    __shared__ __align__(16) uint32_t sB[2][128 * 20];
    const int t = threadIdx.x, lane = t & 31, w = t >> 5;
    const int wr = w >> 1, wc = w & 1;
    const uint32_t sAb = (uint32_t)__cvta_generic_to_shared(&sA[0][0]);
    const uint32_t sBb = (uint32_t)__cvta_generic_to_shared(&sB[0][0]);
    constexpr uint32_t BUFB = 128 * 20 * 4;

    auto loadTiles = [&](int k0, int buf) {
        #pragma unroll
        for (int i = 0; i < 2; i++) {
            int idx = t + (i << 8);
            int row = idx >> 2, c8 = (idx & 3) << 3;
            cp16(sAb + buf * BUFB + (row * 20 + (c8 >> 1)) * 4,
                 A + (size_t)row * lda + k0 + c8);
        }
        #pragma unroll
        for (int i = 0; i < 2; i++) {
            int idx = t + (i << 8);
            int n = idx >> 2, c8 = (idx & 3) << 3;
            cp16(sBb + buf * BUFB + (n * 20 + (c8 >> 1)) * 4,
                 B + (size_t)n * ldb + k0 + c8);
        }
        cp_commit();
    };

    const int nit = CD >> 5;   // 32
    loadTiles(0, 0);
    for (int i = 0; i < nit; i++) {
        if (i + 1 < nit) { loadTiles((i + 1) << 5, (i + 1) & 1); cp_wait1(); }
        else             { cp_wait0(); }
        __syncthreads();
        const uint32_t aBase = sAb + (i & 1) * BUFB;
        const uint32_t bBase = sBb + (i & 1) * BUFB;

        #pragma unroll
        for (int ks = 0; ks < 2; ks++) {
            uint32_t af[2][4], bf[8][2];
            #pragma unroll
            for (int ms = 0; ms < 2; ms++) {
                int row  = wr * 32 + ms * 16 + (lane & 15);
                int word = ks * 8 + ((lane >> 4) << 2);
                ldsm4(af[ms][0], af[ms][1], af[ms][2], af[ms][3],
                      aBase + (row * 20 + word) * 4);
            }
            #pragma unroll
            for (int p = 0; p < 4; p++) {
                int row  = wc * 64 + p * 16 + ((lane >> 4) << 3) + (lane & 7);
                int word = ks * 8 + (((lane >> 3) & 1) << 2);
                ldsm4(bf[2 * p][0], bf[2 * p][1], bf[2 * p + 1][0], bf[2 * p + 1][1],
                      bBase + (row * 20 + word) * 4);
            }
            #pragma unroll
            for (int ms = 0; ms < 2; ms++)
                #pragma unroll
                for (int ns = 0; ns < 8; ns++)
                    mma16(acc[ms][ns], af[ms], bf[ns]);
        }
        __syncthreads();
    }
}

// ---------------- valid-row flags ----------------
__global__ void k_valid(const float* __restrict__ x, float* __restrict__ valid) {
    int row = blockIdx.x;
    const float* xr = x + (size_t)row * CD;
    int any = 0;
    for (int i = threadIdx.x; i < CD; i += blockDim.x) any |= (xr[i] != 0.0f);
    any = __syncthreads_or(any);
    if (threadIdx.x == 0) valid[row] = any ? 1.0f : 0.0f;
}

// ---------------- QKV projection (transposed weights, fp16 in/out) --------------
// grid: (24 = 3 which x 8 head-pairs, 32 row tiles). Q gets 0.125 folded in.
__global__ void __launch_bounds__(256)
k_qkv16(const __half* __restrict__ xh,
        const __half* __restrict__ WqT, const __half* __restrict__ WkT,
        const __half* __restrict__ WvT,
        __half* __restrict__ pQ, __half* __restrict__ pK, __half* __restrict__ pV) {
    int which = blockIdx.x >> 3, hp = blockIdx.x & 7;
    int b = blockIdx.y >> 3, s0 = (blockIdx.y & 7) << 7;
    const __half* W = (which == 0 ? WqT : which == 1 ? WkT : WvT)
                      + (size_t)hp * 128 * CD;   // rows: 2 heads x 64 e
    const __half* A = xh + ((size_t)b * CS + s0) * CD;
    __half* P = (which == 0 ? pQ : which == 1 ? pK : pV);
    const float sc = (which == 0) ? 0.125f : 1.0f;

    float acc[2][8][4] = {};
    gemm16(A, CD, W, CD, acc);

    int lane = threadIdx.x & 31, w = threadIdx.x >> 5, wr = w >> 1, wc = w & 1;
    int head = hp * 2 + wc;
    __half* out = P + ((size_t)(b * 16 + head) * CS + s0) * CDK;
    #pragma unroll
    for (int ms = 0; ms < 2; ms++)
        #pragma unroll
        for (int ns = 0; ns < 8; ns++) {
            int r = wr * 32 + ms * 16 + (lane >> 2);
            int e = ns * 8 + ((lane & 3) << 1);
            *(uint32_t*)&out[(size_t)r * CDK + e] =
                packh2(acc[ms][ns][0] * sc, acc[ms][ns][1] * sc);
            *(uint32_t*)&out[(size_t)(r + 8) * CDK + e] =
                packh2(acc[ms][ns][2] * sc, acc[ms][ns][3] * sc);
        }
}

// ---------------- fused flash attention (fp16, ldmatrix, tile skip) -------------
__global__ void __launch_bounds__(256)
k_flash(const __half* __restrict__ pQ, const __half* __restrict__ pK,
        const __half* __restrict__ pV, const float* __restrict__ valid,
        float* __restrict__ pZ) {
    __shared__ __align__(16) uint32_t sK[64 * 36];
    __shared__ __align__(16) uint32_t sV[64 * 36];
    const int bh = blockIdx.y, b = bh >> 4, h = bh & 15;
    const int q0 = blockIdx.x * 128;
    const int t = threadIdx.x, lane = t & 31, w = t >> 5;
    const int rA = lane >> 2;
    const int qq = lane & 3;
    const float* vbase = valid + b * CS;
    const uint32_t sKb = (uint32_t)__cvta_generic_to_shared(sK);
    const uint32_t sVb = (uint32_t)__cvta_generic_to_shared(sV);
    const int lrow  = ((lane >> 4) << 3) + (lane & 7);
    const int lword = (((lane >> 3) & 1) << 2);

    const __half* Qb = pQ + ((size_t)bh * CS + q0 + w * 16) * CDK;
    uint32_t qf[4][4];
    #pragma unroll
    for (int s = 0; s < 4; s++) {
        int k = s * 16 + (qq << 1);
        qf[s][0] = *(const uint32_t*)(Qb + (size_t)rA * CDK + k);
        qf[s][1] = *(const uint32_t*)(Qb + (size_t)(rA + 8) * CDK + k);
        qf[s][2] = *(const uint32_t*)(Qb + (size_t)rA * CDK + k + 8);
        qf[s][3] = *(const uint32_t*)(Qb + (size_t)(rA + 8) * CDK + k + 8);
    }

    float acc_o[8][4] = {};
    float mA = -INFINITY, mB = -INFINITY, lA = 0.f, lB = 0.f;

    for (int kt = 0; kt < 16; kt++) {
        if (vbase[kt * 64] == 0.f) break;
        __syncthreads();
        const __half* Kg = pK + ((size_t)bh * CS + kt * 64) * CDK;
        const __half* Vg = pV + ((size_t)bh * CS + kt * 64) * CDK;
        #pragma unroll
        for (int i = 0; i < 2; i++) {
            int idx = t + (i << 8);
            int row = idx >> 3, c8 = (idx & 7) << 3;
            *(uint4*)&sK[row * 36 + (c8 >> 1)] =
                *(const uint4*)(Kg + (size_t)row * CDK + c8);
        }
        #pragma unroll
        for (int i = 0; i < 2; i++) {
            int k2 = (t >> 4) + (i << 4);
            int n4 = (t & 15) << 2;
            const __half* vv = Vg + (size_t)(2 * k2) * CDK + n4;
            uint2 v0 = *(const uint2*)vv;
            uint2 v1 = *(const uint2*)(vv + CDK);
            sV[(n4 + 0) * 36 + k2] = __byte_perm(v0.x, v1.x, 0x5410);
            sV[(n4 + 1) * 36 + k2] = __byte_perm(v0.x, v1.x, 0x7632);
            sV[(n4 + 2) * 36 + k2] = __byte_perm(v0.y, v1.y, 0x5410);
            sV[(n4 + 3) * 36 + k2] = __byte_perm(v0.y, v1.y, 0x7632);
        }
        __syncthreads();

        float accs[8][4] = {};
        #pragma unroll
        for (int s = 0; s < 4; s++) {
            #pragma unroll
            for (int p = 0; p < 4; p++) {
                uint32_t bf[4];
                int row = p * 16 + lrow;
                int word = (s << 3) + lword;
                ldsm4(bf[0], bf[1], bf[2], bf[3], sKb + (row * 36 + word) * 4);
                mma16(accs[2 * p],     qf[s], bf);
                mma16(accs[2 * p + 1], qf[s], bf + 2);
            }
        }

        float rmaxA = -INFINITY, rmaxB = -INFINITY;
        #pragma unroll
        for (int j = 0; j < 8; j++) {
            int cg = kt * 64 + j * 8 + (qq << 1);
            float cm0 = vbase[cg], cm1 = vbase[cg + 1];
            accs[j][0] = (cm0 != 0.f) ? accs[j][0] : -1e30f;
            accs[j][1] = (cm1 != 0.f) ? accs[j][1] : -1e30f;
            accs[j][2] = (cm0 != 0.f) ? accs[j][2] : -1e30f;
            accs[j][3] = (cm1 != 0.f) ? accs[j][3] : -1e30f;
            rmaxA = fmaxf(rmaxA, fmaxf(accs[j][0], accs[j][1]));
            rmaxB = fmaxf(rmaxB, fmaxf(accs[j][2], accs[j][3]));
        }
        rmaxA = fmaxf(rmaxA, __shfl_xor_sync(~0u, rmaxA, 1));
        rmaxA = fmaxf(rmaxA, __shfl_xor_sync(~0u, rmaxA, 2));
        rmaxB = fmaxf(rmaxB, __shfl_xor_sync(~0u, rmaxB, 1));
        rmaxB = fmaxf(rmaxB, __shfl_xor_sync(~0u, rmaxB, 2));

        float mnA = fmaxf(mA, rmaxA), mnB = fmaxf(mB, rmaxB);
        float aAf = __expf(mA - mnA), aBf = __expf(mB - mnB);
        mA = mnA; mB = mnB;

        float sumA = 0.f, sumB = 0.f;
        uint32_t pt2[8][2];
        #pragma unroll
        for (int j = 0; j < 8; j++) {
            float p0 = __expf(accs[j][0] - mA), p1 = __expf(accs[j][1] - mA);
            float p2 = __expf(accs[j][2] - mB), p3 = __expf(accs[j][3] - mB);
            sumA += p0 + p1; sumB += p2 + p3;
            pt2[j][0] = packh2(p0, p1);
            pt2[j][1] = packh2(p2, p3);
            acc_o[j][0] *= aAf; acc_o[j][1] *= aAf;
            acc_o[j][2] *= aBf; acc_o[j][3] *= aBf;
        }
        sumA += __shfl_xor_sync(~0u, sumA, 1); sumA += __shfl_xor_sync(~0u, sumA, 2);
        sumB += __shfl_xor_sync(~0u, sumB, 1); sumB += __shfl_xor_sync(~0u, sumB, 2);
        lA = lA * aAf + sumA; lB = lB * aBf + sumB;

        #pragma unroll
        for (int kb = 0; kb < 4; kb++) {
            uint32_t af[4] = { pt2[2 * kb][0], pt2[2 * kb][1],
                               pt2[2 * kb + 1][0], pt2[2 * kb + 1][1] };
            #pragma unroll
            for (int p = 0; p < 4; p++) {
                uint32_t bf[4];
                int row = p * 16 + lrow;
                int word = (kb << 3) + lword;
                ldsm4(bf[0], bf[1], bf[2], bf[3], sVb + (row * 36 + word) * 4);
                mma16(acc_o[2 * p],     af, bf);
                mma16(acc_o[2 * p + 1], af, bf + 2);
            }
        }
    }

    float invA = 1.f / lA, invB = 1.f / lB;
    int qrA = q0 + w * 16 + rA, qrB = qrA + 8;
    float vfA = vbase[qrA] * invA, vfB = vbase[qrB] * invB;
    #pragma unroll
    for (int j = 0; j < 8; j++) {
        int c = j * 8 + (qq << 1);
        float2 v01 = { acc_o[j][0] * vfA, acc_o[j][1] * vfA };
        float2 v23 = { acc_o[j][2] * vfB, acc_o[j][3] * vfB };
        *(float2*)&pZ[(size_t)(b * CS + qrA) * CD + h * 64 + c] = v01;
        *(float2*)&pZ[(size_t)(b * CS + qrB) * CD + h * 64 + c] = v23;
    }
}

// ---------------- residual add + LayerNorm (optional fp16 mirror) ---------------
template<bool H16>
__global__ void k_addln(const float* __restrict__ A, const float* __restrict__ Bv,
                        const float* __restrict__ g, const float* __restrict__ bb,
                        float* __restrict__ out, __half* __restrict__ outh) {
    int row = blockIdx.x, t = threadIdx.x;
    float4 a = ((const float4*)(A  + (size_t)row * CD))[t];
    float4 b = ((const float4*)(Bv + (size_t)row * CD))[t];
    float4 v = {a.x + b.x, a.y + b.y, a.z + b.z, a.w + b.w};
    float s = v.x + v.y + v.z + v.w;
    float q = v.x * v.x + v.y * v.y + v.z * v.z + v.w * v.w;
    __shared__ float sr1[8];
    __shared__ float sr2[8];
    s = warpSum(s); q = warpSum(q);
    if ((t & 31) == 0) { sr1[t >> 5] = s; sr2[t >> 5] = q; }
    __syncthreads();
    float S = 0.f, Q = 0.f;
    #pragma unroll
    for (int i = 0; i < 8; i++) { S += sr1[i]; Q += sr2[i]; }
    float mu = S * (1.0f / CD);
    float var = Q * (1.0f / CD) - mu * mu;
    float rs = rsqrtf(var + LN_EPS);
    float4 gg = ((const float4*)g)[t];
    float4 bv2 = ((const float4*)bb)[t];
    float4 o;
    o.x = (v.x - mu) * rs * gg.x + bv2.x;
    o.y = (v.y - mu) * rs * gg.y + bv2.y;
    o.z = (v.z - mu) * rs * gg.z + bv2.z;
    o.w = (v.w - mu) * rs * gg.w + bv2.w;
    ((float4*)(out + (size_t)row * CD))[t] = o;
    if (H16) {
        uint2 u = { packh2(o.x, o.y), packh2(o.z, o.w) };
        ((uint2*)(outh + (size_t)row * CD))[t] = u;
    }
}

// ---------------- FC1: fp16 in -> relu*valid -> fp16 out ----------------
__global__ void __launch_bounds__(256)
k_fc1(const __half* __restrict__ A, const __half* __restrict__ W,
      const float* __restrict__ bias, const float* __restrict__ valid,
      __half* __restrict__ outh) {
    int j0 = blockIdx.x * 128, r0 = blockIdx.y * 128;
    float acc[2][8][4] = {};
    gemm16(A + (size_t)r0 * CD, CD, W + (size_t)j0 * CD, CD, acc);

    int lane = threadIdx.x & 31, w = threadIdx.x >> 5, wr = w >> 1, wc = w & 1;
    #pragma unroll
    for (int ms = 0; ms < 2; ms++)
        #pragma unroll
        for (int ns = 0; ns < 8; ns++) {
            int r = wr * 32 + ms * 16 + (lane >> 2);
            int c = wc * 64 + ns * 8 + ((lane & 3) << 1);
            float b0 = bias[j0 + c], b1 = bias[j0 + c + 1];
            float vf0 = valid[r0 + r], vf1 = valid[r0 + r + 8];
            float t0 = fmaxf(acc[ms][ns][0] + b0, 0.f) * vf0;
            float t1 = fmaxf(acc[ms][ns][1] + b1, 0.f) * vf0;
            float t2 = fmaxf(acc[ms][ns][2] + b0, 0.f) * vf1;
            float t3 = fmaxf(acc[ms][ns][3] + b1, 0.f) * vf1;
            *(uint32_t*)&outh[(size_t)(r0 + r) * CD + j0 + c]     = packh2(t0, t1);
            *(uint32_t*)&outh[(size_t)(r0 + r + 8) * CD + j0 + c] = packh2(t2, t3);
        }
}

// ---------------- FC2: fp16 in -> +bias, *valid -> fp32 out ----------------
__global__ void __launch_bounds__(256)
k_fc2(const __half* __restrict__ A, const __half* __restrict__ W,
      const float* __restrict__ bias, const float* __restrict__ valid,
      float* __restrict__ out) {
    int j0 = blockIdx.x * 128, r0 = blockIdx.y * 128;
    float acc[2][8][4] = {};
    gemm16(A + (size_t)r0 * CD, CD, W + (size_t)j0 * CD, CD, acc);

    int lane = threadIdx.x & 31, w = threadIdx.x >> 5, wr = w >> 1, wc = w & 1;
    #pragma unroll
    for (int ms = 0; ms < 2; ms++)
        #pragma unroll
        for (int ns = 0; ns < 8; ns++) {
            int r = wr * 32 + ms * 16 + (lane >> 2);
            int c = wc * 64 + ns * 8 + ((lane & 3) << 1);
            float b0 = bias[j0 + c], b1 = bias[j0 + c + 1];
            float vf0 = valid[r0 + r], vf1 = valid[r0 + r + 8];
            float2 v01 = { (acc[ms][ns][0] + b0) * vf0, (acc[ms][ns][1] + b1) * vf0 };
            float2 v23 = { (acc[ms][ns][2] + b0) * vf1, (acc[ms][ns][3] + b1) * vf1 };
            *(float2*)&out[(size_t)(r0 + r) * CD + j0 + c] = v01;
            *(float2*)&out[(size_t)(r0 + r + 8) * CD + j0 + c] = v23;
        }
}

// ---------------- launch ----------------
extern "C" void kernel_launch(void* const* d_in, const int* in_sizes, int n_in,
                              void* d_out, int out_size) {
    const float* x     = (const float*)d_in[0];
    const float* Wq    = (const float*)d_in[1];
    const float* Wk    = (const float*)d_in[2];
    const float* Wv    = (const float*)d_in[3];
    const float* ln1_g = (const float*)d_in[4];
    const float* ln1_b = (const float*)d_in[5];
    const float* fc1_w = (const float*)d_in[6];
    const float* fc1_b = (const float*)d_in[7];
    const float* fc2_w = (const float*)d_in[8];
    const float* fc2_b = (const float*)d_in[9];
    const float* ln2_g = (const float*)d_in[10];
    const float* ln2_b = (const float*)d_in[11];
    float* out = (float*)d_out;

    static float *pValid = nullptr, *pZ, *pH, *pG;
    static __half *pQh, *pKh, *pVh, *pXh, *pWqT, *pWkT, *pWvT, *pW1h, *pW2h, *pHh, *pFh;
    if (!pValid) {
        cudaGetSymbolAddress((void**)&pValid, g_valid);
        cudaGetSymbolAddress((void**)&pZ, g_Z);
        cudaGetSymbolAddress((void**)&pH, g_Hb);
        cudaGetSymbolAddress((void**)&pG, g_G);
        cudaGetSymbolAddress((void**)&pQh, g_Qh);
        cudaGetSymbolAddress((void**)&pKh, g_Kh);
        cudaGetSymbolAddress((void**)&pVh, g_Vh);
        cudaGetSymbolAddress((void**)&pXh, g_xh);
        cudaGetSymbolAddress((void**)&pWqT, g_WqT);
        cudaGetSymbolAddress((void**)&pWkT, g_WkT);
        cudaGetSymbolAddress((void**)&pWvT, g_WvT);
        cudaGetSymbolAddress((void**)&pW1h, g_W1h);
        cudaGetSymbolAddress((void**)&pW2h, g_W2h);
        cudaGetSymbolAddress((void**)&pHh, g_Hh);
        cudaGetSymbolAddress((void**)&pFh, g_Fh);
    }

    k_valid<<<ROWS, 256>>>(x, pValid);
    k_cvt3<<<6144, 256>>>(x, fc1_w, fc2_w, pXh, pW1h, pW2h);
    k_cvtT<<<dim3(16, 16, 3), 256>>>(Wq, Wk, Wv, pWqT, pWkT, pWvT);
    k_qkv16<<<dim3(24, 32), 256>>>(pXh, pWqT, pWkT, pWvT, pQh, pKh, pVh);
    k_flash<<<dim3(8, BH), 256>>>(pQh, pKh, pVh, pValid, pZ);
    k_addln<true><<<ROWS, 256>>>(x, pZ, ln1_g, ln1_b, pH, pHh);
    k_fc1<<<dim3(8, 32), 256>>>(pHh, pW1h, fc1_b, pValid, pFh);
    k_fc2<<<dim3(8, 32), 256>>>(pFh, pW2h, fc2_b, pValid, pG);
    k_addln<false><<<ROWS, 256>>>(pH, pG, ln2_g, ln2_b, out, nullptr);
}

// round 17
// speedup vs baseline: 2.2563x; 1.1227x over previous
#include <cuda_runtime.h>
#include <cuda_fp16.h>
#include <math.h>
#include <stdint.h>

// Problem dims
constexpr int CB  = 4;
constexpr int CS  = 1024;
constexpr int CD  = 1024;
constexpr int CH  = 16;
constexpr int CDK = 64;
constexpr int BH   = CB * CH;   // 64
constexpr int ROWS = CB * CS;   // 4096
constexpr float LN_EPS = 1e-5f;

// GEMM smem: 3 stages x (A 2560 + B 2560 words) x 4 B = 61440 B
constexpr int ABUF  = 128 * 20;          // words per matrix per stage
constexpr int STAGE = 2 * ABUF;          // words per stage
constexpr int GEMM_SMEM = 3 * STAGE * 4; // bytes

// Scratch (device globals: no cudaMalloc allowed)
__device__ float g_valid[ROWS];
__device__ float g_Z[(size_t)ROWS * CD];
__device__ float g_Hb[(size_t)ROWS * CD];
__device__ float g_G[(size_t)ROWS * CD];
// fp16 tensors
__device__ __half g_Qh[(size_t)BH * CS * CDK];
__device__ __half g_Kh[(size_t)BH * CS * CDK];
__device__ __half g_Vh[(size_t)BH * CS * CDK];
__device__ __half g_xh[(size_t)ROWS * CD];
__device__ __half g_WqT[(size_t)CH * CDK * CD];   // transposed: [h][e][d]
__device__ __half g_WkT[(size_t)CH * CDK * CD];
__device__ __half g_WvT[(size_t)CH * CDK * CD];
__device__ __half g_W1h[(size_t)CD * CD];
__device__ __half g_W2h[(size_t)CD * CD];
__device__ __half g_Hh[(size_t)ROWS * CD];
__device__ __half g_Fh[(size_t)ROWS * CD];

// ---------------- helpers ----------------
__device__ __forceinline__ float warpSum(float v) {
    #pragma unroll
    for (int o = 16; o; o >>= 1) v += __shfl_xor_sync(0xffffffffu, v, o);
    return v;
}
__device__ __forceinline__ uint32_t packh2(float lo, float hi) {
    __half2 h = __floats2half2_rn(lo, hi);
    return *reinterpret_cast<uint32_t*>(&h);
}
__device__ __forceinline__ void mma16(float c[4], const uint32_t a[4], const uint32_t b[2]) {
    asm volatile(
        "mma.sync.aligned.m16n8k16.row.col.f32.f16.f16.f32 "
        "{%0,%1,%2,%3},{%4,%5,%6,%7},{%8,%9},{%0,%1,%2,%3};"
        : "+f"(c[0]), "+f"(c[1]), "+f"(c[2]), "+f"(c[3])
        : "r"(a[0]), "r"(a[1]), "r"(a[2]), "r"(a[3]), "r"(b[0]), "r"(b[1]));
}
__device__ __forceinline__ void ldsm4(uint32_t& r0, uint32_t& r1, uint32_t& r2, uint32_t& r3,
                                      uint32_t saddr) {
    asm volatile("ldmatrix.sync.aligned.m8n8.x4.shared.b16 {%0,%1,%2,%3}, [%4];"
        : "=r"(r0), "=r"(r1), "=r"(r2), "=r"(r3) : "r"(saddr));
}
__device__ __forceinline__ void cp16(uint32_t sdst, const void* gsrc) {
    asm volatile("cp.async.cg.shared.global [%0], [%1], 16;" :: "r"(sdst), "l"(gsrc));
}
__device__ __forceinline__ void cp_commit() { asm volatile("cp.async.commit_group;"); }
__device__ __forceinline__ void cp_wait1()  { asm volatile("cp.async.wait_group 1;"); }
__device__ __forceinline__ void cp_wait0()  { asm volatile("cp.async.wait_group 0;"); }

// ---------------- fp32 -> fp16 convert (x + fc weights) + valid flags ----------
__global__ void k_cvt3v(const float* __restrict__ x, const float* __restrict__ w1,
                        const float* __restrict__ w2,
                        __half* xh, __half* w1h, __half* w2h, float* __restrict__ valid) {
    int bid = blockIdx.x;
    if (bid < 4096) {
        int i = bid * 256 + threadIdx.x;
        float4 v = ((const float4*)x)[i];
        uint2 u = { packh2(v.x, v.y), packh2(v.z, v.w) };
        ((uint2*)xh)[i] = u;
        int any = (v.x != 0.f) | (v.y != 0.f) | (v.z != 0.f) | (v.w != 0.f);
        any = __syncthreads_or(any);
        if (threadIdx.x == 0) valid[bid] = any ? 1.0f : 0.0f;
    } else {
        const float* s; __half* d; int off;
        if (bid < 5120) { s = w1; d = w1h; off = bid - 4096; }
        else            { s = w2; d = w2h; off = bid - 5120; }
        int i = off * 256 + threadIdx.x;
        float4 v = ((const float4*)s)[i];
        uint2 u = { packh2(v.x, v.y), packh2(v.z, v.w) };
        ((uint2*)d)[i] = u;
    }
}

// ---------------- QKV weight transpose+convert: [h][d][e] -> [h][e][d] ----------
__global__ void k_cvtT(const float* __restrict__ wq, const float* __restrict__ wk,
                       const float* __restrict__ wv,
                       __half* wqt, __half* wkt, __half* wvt) {
    int which = blockIdx.z;
    const float* s = which == 0 ? wq : which == 1 ? wk : wv;
    __half* d = which == 0 ? wqt : which == 1 ? wkt : wvt;
    int h = blockIdx.y, d0 = blockIdx.x * 64;
    __shared__ __half sh[64][72];
    const float* base = s + ((size_t)h * CD + d0) * CDK;
    int t = threadIdx.x;
    #pragma unroll
    for (int p = 0; p < 4; p++) {
        int dr = (t >> 4) + p * 16;
        int e4 = (t & 15) << 2;
        float4 v = *(const float4*)(base + (size_t)dr * CDK + e4);
        sh[dr][e4]     = __float2half_rn(v.x);
        sh[dr][e4 + 1] = __float2half_rn(v.y);
        sh[dr][e4 + 2] = __float2half_rn(v.z);
        sh[dr][e4 + 3] = __float2half_rn(v.w);
    }
    __syncthreads();
    __half* ob = d + (size_t)h * CDK * CD + d0;
    #pragma unroll
    for (int p = 0; p < 2; p++) {
        int idx = t + (p << 8);
        int e = idx >> 3, dq = (idx & 7) << 3;
        __half tmp[8];
        #pragma unroll
        for (int j = 0; j < 8; j++) tmp[j] = sh[dq + j][e];
        *(uint4*)(ob + (size_t)e * CD + dq) = *(uint4*)tmp;
    }
}

// ---------------- fp16 MMA GEMM core: 128x128, 3-stage cp.async -----------------
// BK=32, 256 threads = 8 warps (4 row x 2 col); warp tile 32(M) x 64(N).
// A[m][k] lda, B[n][k] ldb, row-major fp16. smem stride 20 words, dynamic.
__device__ __forceinline__ void gemm16(const __half* __restrict__ A, int lda,
                                       const __half* __restrict__ B, int ldb,
                                       float acc[2][8][4]) {
    extern __shared__ __align__(16) uint32_t dyn[];
    const int t = threadIdx.x, lane = t & 31, w = t >> 5;
    const int wr = w >> 1, wc = w & 1;
    const uint32_t sBase = (uint32_t)__cvta_generic_to_shared(dyn);

    auto loadTiles = [&](int k0, int st) {
        uint32_t aOff = sBase + (uint32_t)(st * STAGE) * 4;
        uint32_t bOff = aOff + (uint32_t)ABUF * 4;
        #pragma unroll
        for (int i = 0; i < 2; i++) {
            int idx = t + (i << 8);
            int row = idx >> 2, c8 = (idx & 3) << 3;
            cp16(aOff + (row * 20 + (c8 >> 1)) * 4, A + (size_t)row * lda + k0 + c8);
        }
        #pragma unroll
        for (int i = 0; i < 2; i++) {
            int idx = t + (i << 8);
            int n = idx >> 2, c8 = (idx & 3) << 3;
            cp16(bOff + (n * 20 + (c8 >> 1)) * 4, B + (size_t)n * ldb + k0 + c8);
        }
        cp_commit();
    };

    const int nit = CD >> 5;   // 32
    loadTiles(0, 0);
    loadTiles(32, 1);
    int st = 0;
    for (int i = 0; i < nit; i++) {
        if (i < nit - 1) cp_wait1(); else cp_wait0();
        __syncthreads();
        const uint32_t aBase = sBase + (uint32_t)(st * STAGE) * 4;
        const uint32_t bBase = aBase + (uint32_t)ABUF * 4;

        #pragma unroll
        for (int ks = 0; ks < 2; ks++) {
            uint32_t af[2][4], bf[8][2];
            #pragma unroll
            for (int ms = 0; ms < 2; ms++) {
                int row  = wr * 32 + ms * 16 + (lane & 15);
                int word = ks * 8 + ((lane >> 4) << 2);
                ldsm4(af[ms][0], af[ms][1], af[ms][2], af[ms][3],
                      aBase + (row * 20 + word) * 4);
            }
            #pragma unroll
            for (int p = 0; p < 4; p++) {
                int row  = wc * 64 + p * 16 + ((lane >> 4) << 3) + (lane & 7);
                int word = ks * 8 + (((lane >> 3) & 1) << 2);
                ldsm4(bf[2 * p][0], bf[2 * p][1], bf[2 * p + 1][0], bf[2 * p + 1][1],
                      bBase + (row * 20 + word) * 4);
            }
            #pragma unroll
            for (int ms = 0; ms < 2; ms++)
                #pragma unroll
                for (int ns = 0; ns < 8; ns++)
                    mma16(acc[ms][ns], af[ms], bf[ns]);
        }
        if (i + 2 < nit) {
            int st2 = st + 2; if (st2 >= 3) st2 -= 3;
            loadTiles((i + 2) << 5, st2);
        }
        if (++st == 3) st = 0;
    }
}

// ---------------- QKV projection (transposed weights, fp16 in/out) --------------
__global__ void __launch_bounds__(256)
k_qkv16(const __half* __restrict__ xh,
        const __half* __restrict__ WqT, const __half* __restrict__ WkT,
        const __half* __restrict__ WvT,
        __half* __restrict__ pQ, __half* __restrict__ pK, __half* __restrict__ pV) {
    int which = blockIdx.x >> 3, hp = blockIdx.x & 7;
    int b = blockIdx.y >> 3, s0 = (blockIdx.y & 7) << 7;
    const __half* W = (which == 0 ? WqT : which == 1 ? WkT : WvT)
                      + (size_t)hp * 128 * CD;
    const __half* A = xh + ((size_t)b * CS + s0) * CD;
    __half* P = (which == 0 ? pQ : which == 1 ? pK : pV);
    const float sc = (which == 0) ? 0.125f : 1.0f;

    float acc[2][8][4] = {};
    gemm16(A, CD, W, CD, acc);

    int lane = threadIdx.x & 31, w = threadIdx.x >> 5, wr = w >> 1, wc = w & 1;
    int head = hp * 2 + wc;
    __half* out = P + ((size_t)(b * 16 + head) * CS + s0) * CDK;
    #pragma unroll
    for (int ms = 0; ms < 2; ms++)
        #pragma unroll
        for (int ns = 0; ns < 8; ns++) {
            int r = wr * 32 + ms * 16 + (lane >> 2);
            int e = ns * 8 + ((lane & 3) << 1);
            *(uint32_t*)&out[(size_t)r * CDK + e] =
                packh2(acc[ms][ns][0] * sc, acc[ms][ns][1] * sc);
            *(uint32_t*)&out[(size_t)(r + 8) * CDK + e] =
                packh2(acc[ms][ns][2] * sc, acc[ms][ns][3] * sc);
        }
}

// ---------------- fused flash attention (fp16, ldmatrix, tile skip) -------------
__global__ void __launch_bounds__(256)
k_flash(const __half* __restrict__ pQ, const __half* __restrict__ pK,
        const __half* __restrict__ pV, const float* __restrict__ valid,
        float* __restrict__ pZ) {
    __shared__ __align__(16) uint32_t sK[64 * 36];
    __shared__ __align__(16) uint32_t sV[64 * 36];
    const int bh = blockIdx.y, b = bh >> 4, h = bh & 15;
    const int q0 = blockIdx.x * 128;
    const int t = threadIdx.x, lane = t & 31, w = t >> 5;
    const int rA = lane >> 2;
    const int qq = lane & 3;
    const float* vbase = valid + b * CS;
    const uint32_t sKb = (uint32_t)__cvta_generic_to_shared(sK);
    const uint32_t sVb = (uint32_t)__cvta_generic_to_shared(sV);
    const int lrow  = ((lane >> 4) << 3) + (lane & 7);
    const int lword = (((lane >> 3) & 1) << 2);

    const __half* Qb = pQ + ((size_t)bh * CS + q0 + w * 16) * CDK;
    uint32_t qf[4][4];
    #pragma unroll
    for (int s = 0; s < 4; s++) {
        int k = s * 16 + (qq << 1);
        qf[s][0] = *(const uint32_t*)(Qb + (size_t)rA * CDK + k);
        qf[s][1] = *(const uint32_t*)(Qb + (size_t)(rA + 8) * CDK + k);
        qf[s][2] = *(const uint32_t*)(Qb + (size_t)rA * CDK + k + 8);
        qf[s][3] = *(const uint32_t*)(Qb + (size_t)(rA + 8) * CDK + k + 8);
    }

    float acc_o[8][4] = {};
    float mA = -INFINITY, mB = -INFINITY, lA = 0.f, lB = 0.f;

    for (int kt = 0; kt < 16; kt++) {
        if (vbase[kt * 64] == 0.f) break;
        __syncthreads();
        const __half* Kg = pK + ((size_t)bh * CS + kt * 64) * CDK;
        const __half* Vg = pV + ((size_t)bh * CS + kt * 64) * CDK;
        #pragma unroll
        for (int i = 0; i < 2; i++) {
            int idx = t + (i << 8);
            int row = idx >> 3, c8 = (idx & 7) << 3;
            *(uint4*)&sK[row * 36 + (c8 >> 1)] =
                *(const uint4*)(Kg + (size_t)row * CDK + c8);
        }
        #pragma unroll
        for (int i = 0; i < 2; i++) {
            int k2 = (t >> 4) + (i << 4);
            int n4 = (t & 15) << 2;
            const __half* vv = Vg + (size_t)(2 * k2) * CDK + n4;
            uint2 v0 = *(const uint2*)vv;
            uint2 v1 = *(const uint2*)(vv + CDK);
            sV[(n4 + 0) * 36 + k2] = __byte_perm(v0.x, v1.x, 0x5410);
            sV[(n4 + 1) * 36 + k2] = __byte_perm(v0.x, v1.x, 0x7632);
            sV[(n4 + 2) * 36 + k2] = __byte_perm(v0.y, v1.y, 0x5410);
            sV[(n4 + 3) * 36 + k2] = __byte_perm(v0.y, v1.y, 0x7632);
        }
        __syncthreads();

        float accs[8][4] = {};
        #pragma unroll
        for (int s = 0; s < 4; s++) {
            #pragma unroll
            for (int p = 0; p < 4; p++) {
                uint32_t bf[4];
                int row = p * 16 + lrow;
                int word = (s << 3) + lword;
                ldsm4(bf[0], bf[1], bf[2], bf[3], sKb + (row * 36 + word) * 4);
                mma16(accs[2 * p],     qf[s], bf);
                mma16(accs[2 * p + 1], qf[s], bf + 2);
            }
        }

        float rmaxA = -INFINITY, rmaxB = -INFINITY;
        #pragma unroll
        for (int j = 0; j < 8; j++) {
            int cg = kt * 64 + j * 8 + (qq << 1);
            float cm0 = vbase[cg], cm1 = vbase[cg + 1];
            accs[j][0] = (cm0 != 0.f) ? accs[j][0] : -1e30f;
            accs[j][1] = (cm1 != 0.f) ? accs[j][1] : -1e30f;
            accs[j][2] = (cm0 != 0.f) ? accs[j][2] : -1e30f;
            accs[j][3] = (cm1 != 0.f) ? accs[j][3] : -1e30f;
            rmaxA = fmaxf(rmaxA, fmaxf(accs[j][0], accs[j][1]));
            rmaxB = fmaxf(rmaxB, fmaxf(accs[j][2], accs[j][3]));
        }
        rmaxA = fmaxf(rmaxA, __shfl_xor_sync(~0u, rmaxA, 1));
        rmaxA = fmaxf(rmaxA, __shfl_xor_sync(~0u, rmaxA, 2));
        rmaxB = fmaxf(rmaxB, __shfl_xor_sync(~0u, rmaxB, 1));
        rmaxB = fmaxf(rmaxB, __shfl_xor_sync(~0u, rmaxB, 2));

        float mnA = fmaxf(mA, rmaxA), mnB = fmaxf(mB, rmaxB);
        float aAf = __expf(mA - mnA), aBf = __expf(mB - mnB);
        mA = mnA; mB = mnB;

        float sumA = 0.f, sumB = 0.f;
        uint32_t pt2[8][2];
        #pragma unroll
        for (int j = 0; j < 8; j++) {
            float p0 = __expf(accs[j][0] - mA), p1 = __expf(accs[j][1] - mA);
            float p2 = __expf(accs[j][2] - mB), p3 = __expf(accs[j][3] - mB);
            sumA += p0 + p1; sumB += p2 + p3;
            pt2[j][0] = packh2(p0, p1);
            pt2[j][1] = packh2(p2, p3);
            acc_o[j][0] *= aAf; acc_o[j][1] *= aAf;
            acc_o[j][2] *= aBf; acc_o[j][3] *= aBf;
        }
        sumA += __shfl_xor_sync(~0u, sumA, 1); sumA += __shfl_xor_sync(~0u, sumA, 2);
        sumB += __shfl_xor_sync(~0u, sumB, 1); sumB += __shfl_xor_sync(~0u, sumB, 2);
        lA = lA * aAf + sumA; lB = lB * aBf + sumB;

        #pragma unroll
        for (int kb = 0; kb < 4; kb++) {
            uint32_t af[4] = { pt2[2 * kb][0], pt2[2 * kb][1],
                               pt2[2 * kb + 1][0], pt2[2 * kb + 1][1] };
            #pragma unroll
            for (int p = 0; p < 4; p++) {
                uint32_t bf[4];
                int row = p * 16 + lrow;
                int word = (kb << 3) + lword;
                ldsm4(bf[0], bf[1], bf[2], bf[3], sVb + (row * 36 + word) * 4);
                mma16(acc_o[2 * p],     af, bf);
                mma16(acc_o[2 * p + 1], af, bf + 2);
            }
        }
    }

    float invA = 1.f / lA, invB = 1.f / lB;
    int qrA = q0 + w * 16 + rA, qrB = qrA + 8;
    float vfA = vbase[qrA] * invA, vfB = vbase[qrB] * invB;
    #pragma unroll
    for (int j = 0; j < 8; j++) {
        int c = j * 8 + (qq << 1);
        float2 v01 = { acc_o[j][0] * vfA, acc_o[j][1] * vfA };
        float2 v23 = { acc_o[j][2] * vfB, acc_o[j][3] * vfB };
        *(float2*)&pZ[(size_t)(b * CS + qrA) * CD + h * 64 + c] = v01;
        *(float2*)&pZ[(size_t)(b * CS + qrB) * CD + h * 64 + c] = v23;
    }
}

// ---------------- residual add + LayerNorm (optional fp16 mirror) ---------------
template<bool H16>
__global__ void k_addln(const float* __restrict__ A, const float* __restrict__ Bv,
                        const float* __restrict__ g, const float* __restrict__ bb,
                        float* __restrict__ out, __half* __restrict__ outh) {
    int row = blockIdx.x, t = threadIdx.x;
    float4 a = ((const float4*)(A  + (size_t)row * CD))[t];
    float4 b = ((const float4*)(Bv + (size_t)row * CD))[t];
    float4 v = {a.x + b.x, a.y + b.y, a.z + b.z, a.w + b.w};
    float s = v.x + v.y + v.z + v.w;
    float q = v.x * v.x + v.y * v.y + v.z * v.z + v.w * v.w;
    __shared__ float sr1[8];
    __shared__ float sr2[8];
    s = warpSum(s); q = warpSum(q);
    if ((t & 31) == 0) { sr1[t >> 5] = s; sr2[t >> 5] = q; }
    __syncthreads();
    float S = 0.f, Q = 0.f;
    #pragma unroll
    for (int i = 0; i < 8; i++) { S += sr1[i]; Q += sr2[i]; }
    float mu = S * (1.0f / CD);
    float var = Q * (1.0f / CD) - mu * mu;
    float rs = rsqrtf(var + LN_EPS);
    float4 gg = ((const float4*)g)[t];
    float4 bv2 = ((const float4*)bb)[t];
    float4 o;
    o.x = (v.x - mu) * rs * gg.x + bv2.x;
    o.y = (v.y - mu) * rs * gg.y + bv2.y;
    o.z = (v.z - mu) * rs * gg.z + bv2.z;
    o.w = (v.w - mu) * rs * gg.w + bv2.w;
    ((float4*)(out + (size_t)row * CD))[t] = o;
    if (H16) {
        uint2 u = { packh2(o.x, o.y), packh2(o.z, o.w) };
        ((uint2*)(outh + (size_t)row * CD))[t] = u;
    }
}

// ---------------- FC1: fp16 in -> relu*valid -> fp16 out ----------------
__global__ void __launch_bounds__(256)
k_fc1(const __half* __restrict__ A, const __half* __restrict__ W,
      const float* __restrict__ bias, const float* __restrict__ valid,
      __half* __restrict__ outh) {
    int j0 = blockIdx.x * 128, r0 = blockIdx.y * 128;
    float acc[2][8][4] = {};
    gemm16(A + (size_t)r0 * CD, CD, W + (size_t)j0 * CD, CD, acc);

    int lane = threadIdx.x & 31, w = threadIdx.x >> 5, wr = w >> 1, wc = w & 1;
    #pragma unroll
    for (int ms = 0; ms < 2; ms++)
        #pragma unroll
        for (int ns = 0; ns < 8; ns++) {
            int r = wr * 32 + ms * 16 + (lane >> 2);
            int c = wc * 64 + ns * 8 + ((lane & 3) << 1);
            float b0 = bias[j0 + c], b1 = bias[j0 + c + 1];
            float vf0 = valid[r0 + r], vf1 = valid[r0 + r + 8];
            float t0 = fmaxf(acc[ms][ns][0] + b0, 0.f) * vf0;
            float t1 = fmaxf(acc[ms][ns][1] + b1, 0.f) * vf0;
            float t2 = fmaxf(acc[ms][ns][2] + b0, 0.f) * vf1;
            float t3 = fmaxf(acc[ms][ns][3] + b1, 0.f) * vf1;
            *(uint32_t*)&outh[(size_t)(r0 + r) * CD + j0 + c]     = packh2(t0, t1);
            *(uint32_t*)&outh[(size_t)(r0 + r + 8) * CD + j0 + c] = packh2(t2, t3);
        }
}

// ---------------- FC2: fp16 in -> +bias, *valid -> fp32 out ----------------
__global__ void __launch_bounds__(256)
k_fc2(const __half* __restrict__ A, const __half* __restrict__ W,
      const float* __restrict__ bias, const float* __restrict__ valid,
      float* __restrict__ out) {
    int j0 = blockIdx.x * 128, r0 = blockIdx.y * 128;
    float acc[2][8][4] = {};
    gemm16(A + (size_t)r0 * CD, CD, W + (size_t)j0 * CD, CD, acc);

    int lane = threadIdx.x & 31, w = threadIdx.x >> 5, wr = w >> 1, wc = w & 1;
    #pragma unroll
    for (int ms = 0; ms < 2; ms++)
        #pragma unroll
        for (int ns = 0; ns < 8; ns++) {
            int r = wr * 32 + ms * 16 + (lane >> 2);
            int c = wc * 64 + ns * 8 + ((lane & 3) << 1);
            float b0 = bias[j0 + c], b1 = bias[j0 + c + 1];
            float vf0 = valid[r0 + r], vf1 = valid[r0 + r + 8];
            float2 v01 = { (acc[ms][ns][0] + b0) * vf0, (acc[ms][ns][1] + b1) * vf0 };
            float2 v23 = { (acc[ms][ns][2] + b0) * vf1, (acc[ms][ns][3] + b1) * vf1 };
            *(float2*)&out[(size_t)(r0 + r) * CD + j0 + c] = v01;
            *(float2*)&out[(size_t)(r0 + r + 8) * CD + j0 + c] = v23;
        }
}

// ---------------- launch ----------------
extern "C" void kernel_launch(void* const* d_in, const int* in_sizes, int n_in,
                              void* d_out, int out_size) {
    const float* x     = (const float*)d_in[0];
    const float* Wq    = (const float*)d_in[1];
    const float* Wk    = (const float*)d_in[2];
    const float* Wv    = (const float*)d_in[3];
    const float* ln1_g = (const float*)d_in[4];
    const float* ln1_b = (const float*)d_in[5];
    const float* fc1_w = (const float*)d_in[6];
    const float* fc1_b = (const float*)d_in[7];
    const float* fc2_w = (const float*)d_in[8];
    const float* fc2_b = (const float*)d_in[9];
    const float* ln2_g = (const float*)d_in[10];
    const float* ln2_b = (const float*)d_in[11];
    float* out = (float*)d_out;

    static float *pValid = nullptr, *pZ, *pH, *pG;
    static __half *pQh, *pKh, *pVh, *pXh, *pWqT, *pWkT, *pWvT, *pW1h, *pW2h, *pHh, *pFh;
    if (!pValid) {
        cudaGetSymbolAddress((void**)&pValid, g_valid);
        cudaGetSymbolAddress((void**)&pZ, g_Z);
        cudaGetSymbolAddress((void**)&pH, g_Hb);
        cudaGetSymbolAddress((void**)&pG, g_G);
        cudaGetSymbolAddress((void**)&pQh, g_Qh);
        cudaGetSymbolAddress((void**)&pKh, g_Kh);
        cudaGetSymbolAddress((void**)&pVh, g_Vh);
        cudaGetSymbolAddress((void**)&pXh, g_xh);
        cudaGetSymbolAddress((void**)&pWqT, g_WqT);
        cudaGetSymbolAddress((void**)&pWkT, g_WkT);
        cudaGetSymbolAddress((void**)&pWvT, g_WvT);
        cudaGetSymbolAddress((void**)&pW1h, g_W1h);
        cudaGetSymbolAddress((void**)&pW2h, g_W2h);
        cudaGetSymbolAddress((void**)&pHh, g_Hh);
        cudaGetSymbolAddress((void**)&pFh, g_Fh);
        cudaFuncSetAttribute(k_qkv16, cudaFuncAttributeMaxDynamicSharedMemorySize, GEMM_SMEM);
        cudaFuncSetAttribute(k_fc1,   cudaFuncAttributeMaxDynamicSharedMemorySize, GEMM_SMEM);
        cudaFuncSetAttribute(k_fc2,   cudaFuncAttributeMaxDynamicSharedMemorySize, GEMM_SMEM);
    }

    k_cvt3v<<<6144, 256>>>(x, fc1_w, fc2_w, pXh, pW1h, pW2h, pValid);
    k_cvtT<<<dim3(16, 16, 3), 256>>>(Wq, Wk, Wv, pWqT, pWkT, pWvT);
    k_qkv16<<<dim3(24, 32), 256, GEMM_SMEM>>>(pXh, pWqT, pWkT, pWvT, pQh, pKh, pVh);
    k_flash<<<dim3(8, BH), 256>>>(pQh, pKh, pVh, pValid, pZ);
    k_addln<true><<<ROWS, 256>>>(x, pZ, ln1_g, ln1_b, pH, pHh);
    k_fc1<<<dim3(8, 32), 256, GEMM_SMEM>>>(pHh, pW1h, fc1_b, pValid, pFh);
    k_fc2<<<dim3(8, 32), 256, GEMM_SMEM>>>(pFh, pW2h, fc2_b, pValid, pG);
    k_addln<false><<<ROWS, 256>>>(pH, pG, ln2_g, ln2_b, out, nullptr);
}